// round 1
// baseline (speedup 1.0000x reference)
#include <cuda_runtime.h>
#include <math.h>

#define B_   32
#define N_   4096
#define S_   512
#define KNN_ 32
#define FULLMASK 0xffffffffu

// ---------------- device scratch (static, allocation-free) ----------------
__device__ float g_centroid[B_ * S_ * 3];
__device__ float g_groups[B_ * S_ * 3 * KNN_];   // [bs][c][k]

// ============================ FPS =========================================
// one block per batch; 512 threads x 8 points each, kept in registers
__global__ __launch_bounds__(512) void fps_kernel(const float* __restrict__ x,
                                                  float* __restrict__ out) {
    int b   = blockIdx.x;
    int tid = threadIdx.x;
    int lane = tid & 31, warp = tid >> 5;
    const float* xb = x + (size_t)b * N_ * 3;

    float px[8], py[8], pz[8], dist[8];
#pragma unroll
    for (int i = 0; i < 8; ++i) {
        int n = tid + i * 512;
        px[i] = xb[n * 3 + 0];
        py[i] = xb[n * 3 + 1];
        pz[i] = xb[n * 3 + 2];
        dist[i] = 1e10f;
    }

    __shared__ float sc[3];
    __shared__ float swv[16];
    __shared__ int   swi[16];
    __shared__ int   s_last;

    int last = 0;
    for (int s = 0; s < S_; ++s) {
        // owner of 'last' publishes its coords
        if ((last & 511) == tid) {
            int slot = last >> 9;
            sc[0] = px[slot]; sc[1] = py[slot]; sc[2] = pz[slot];
        }
        __syncthreads();
        float c0 = sc[0], c1 = sc[1], c2 = sc[2];
        if (tid == 0) {
            int bs = b * S_ + s;
            out[(size_t)bs * 67 + 0] = c0;
            out[(size_t)bs * 67 + 1] = c1;
            out[(size_t)bs * 67 + 2] = c2;
            g_centroid[bs * 3 + 0] = c0;
            g_centroid[bs * 3 + 1] = c1;
            g_centroid[bs * 3 + 2] = c2;
        }

        float bv = -1.0f; int bi = 0x7fffffff;
#pragma unroll
        for (int i = 0; i < 8; ++i) {
            float dx = px[i] - c0, dy = py[i] - c1, dz = pz[i] - c2;
            float d = (dx * dx + dy * dy) + dz * dz;
            float nd = fminf(dist[i], d);
            dist[i] = nd;
            int idx = tid + i * 512;
            if (nd > bv || (nd == bv && idx < bi)) { bv = nd; bi = idx; }
        }
        // warp argmax (first-index on ties)
#pragma unroll
        for (int off = 16; off; off >>= 1) {
            float ov = __shfl_down_sync(FULLMASK, bv, off);
            int   oi = __shfl_down_sync(FULLMASK, bi, off);
            if (ov > bv || (ov == bv && oi < bi)) { bv = ov; bi = oi; }
        }
        if (lane == 0) { swv[warp] = bv; swi[warp] = bi; }
        __syncthreads();
        if (warp == 0) {
            float v2 = (lane < 16) ? swv[lane] : -1.0f;
            int   i2 = (lane < 16) ? swi[lane] : 0x7fffffff;
#pragma unroll
            for (int off = 16; off; off >>= 1) {
                float ov = __shfl_down_sync(FULLMASK, v2, off);
                int   oi = __shfl_down_sync(FULLMASK, i2, off);
                if (ov > v2 || (ov == v2 && oi < i2)) { v2 = ov; i2 = oi; }
            }
            if (lane == 0) s_last = i2;
        }
        __syncthreads();
        last = s_last;
    }
}

// ============================ KNN top-32 ==================================
// 4 blocks per batch, 512 threads. x[b] staged in shared (64KB).
// One warp = one centroid at a time; sorted top-32 list kept one entry/lane.
__global__ __launch_bounds__(512) void knn_kernel(const float* __restrict__ x) {
    int b    = blockIdx.x >> 2;
    int part = blockIdx.x & 3;
    extern __shared__ float smk[];
    float* sx0 = smk;
    float* sx1 = smk + 4096;
    float* sx2 = smk + 8192;
    float* sxs = smk + 12288;

    const float* xb = x + (size_t)b * N_ * 3;
    for (int i = threadIdx.x; i < N_; i += 512) {
        float a0 = xb[i * 3 + 0], a1 = xb[i * 3 + 1], a2 = xb[i * 3 + 2];
        sx0[i] = a0; sx1[i] = a1; sx2[i] = a2;
        sxs[i] = (a0 * a0 + a1 * a1) + a2 * a2;
    }
    __syncthreads();

    int warp = threadIdx.x >> 5, lane = threadIdx.x & 31;
    for (int j = 0; j < 8; ++j) {
        int s  = part * 128 + j * 16 + warp;
        int bs = b * S_ + s;
        float c0 = g_centroid[bs * 3 + 0];
        float c1 = g_centroid[bs * 3 + 1];
        float c2 = g_centroid[bs * 3 + 2];
        float cs = (c0 * c0 + c1 * c1) + c2 * c2;

        float lv = 3.402823466e38f;   // sorted ascending, lane31 = current max
        int   li = -1;
        for (int base = 0; base < N_; base += 32) {
            int n = base + lane;
            float dot = (c0 * sx0[n] + c1 * sx1[n]) + c2 * sx2[n];
            float d2  = (cs + sxs[n]) - 2.0f * dot;
            float thr = __shfl_sync(FULLMASK, lv, 31);
            unsigned m = __ballot_sync(FULLMASK, d2 < thr);
            while (m) {
                int src = __ffs(m) - 1;
                m &= m - 1;
                float cd = __shfl_sync(FULLMASK, d2, src);
                int   cn = base + src;
                thr = __shfl_sync(FULLMASK, lv, 31);
                if (cd < thr) {   // strict < : smaller-index wins on ties
                    unsigned keep = __ballot_sync(FULLMASK,
                        (lv < cd) || (lv == cd && li < cn));
                    int pos = __popc(keep);
                    float pv = __shfl_up_sync(FULLMASK, lv, 1);
                    int   pi = __shfl_up_sync(FULLMASK, li, 1);
                    if (lane == pos)      { lv = cd; li = cn; }
                    else if (lane > pos)  { lv = pv; li = pi; }
                }
            }
        }
        // emit grouped coords (x[knn] - centroid), layout [bs][c][k]
        float gx = sx0[li] - c0, gy = sx1[li] - c1, gz = sx2[li] - c2;
        float* gp = g_groups + (size_t)bs * 96;
        gp[lane]      = gx;
        gp[32 + lane] = gy;
        gp[64 + lane] = gz;
    }
}

// ======================= per-group dense compute ==========================
// 148 persistent blocks x 512 threads. All weights (transposed) in shared.
// warp w owns output rows 4w..4w+3 ; lane = column k.
__device__ __forceinline__ float gelu_exact(float v) {
    return 0.5f * v * (1.0f + erff(v * 0.70710678118654752440f));
}

__global__ __launch_bounds__(512) void group_kernel(
    const float* __restrict__ w_alpha, const float* __restrict__ b_alpha,
    const float* __restrict__ bn_gamma, const float* __restrict__ bn_beta,
    const float* __restrict__ bn_mean,  const float* __restrict__ bn_var,
    const float* __restrict__ w_q, const float* __restrict__ b_q,
    const float* __restrict__ w_k, const float* __restrict__ b_k,
    const float* __restrict__ w_v, const float* __restrict__ b_v,
    const float* __restrict__ w_g1, const float* __restrict__ b_g1,
    const float* __restrict__ w_g2, const float* __restrict__ b_g2,
    float* __restrict__ out) {
    extern __shared__ float sm[];
    const int WQ = 0, WK = 4096, WV = 8192, WG1 = 12288, WG2 = 16384, WA = 20480,
              BQ = 20672, BK = 20736, BV = 20800, BG1 = 20864, BG2 = 20928,
              BA = 20992, BNM = 21056, BNR = 21120, BNG = 21184, BNB = 21248,
              Hb = 21312, Qb = 23360, Kb = 25408, Vb = 27456, RESb = 29504,
              ATT = 31552;   // 32x33 padded -> total 32608 floats

    int tid = threadIdx.x;
    // stage weights (transposed to [c][d]) + biases + BN constants
    for (int i = tid; i < 4096; i += 512) {
        int d = i >> 6, c = i & 63;
        sm[WQ  + c * 64 + d] = w_q[i];
        sm[WK  + c * 64 + d] = w_k[i];
        sm[WV  + c * 64 + d] = w_v[i];
        sm[WG1 + c * 64 + d] = w_g1[i];
        sm[WG2 + c * 64 + d] = w_g2[i];
    }
    if (tid < 192) { int d = tid / 3, c = tid % 3; sm[WA + c * 64 + d] = w_alpha[tid]; }
    if (tid < 64) {
        sm[BQ + tid] = b_q[tid];  sm[BK + tid] = b_k[tid];  sm[BV + tid] = b_v[tid];
        sm[BG1 + tid] = b_g1[tid]; sm[BG2 + tid] = b_g2[tid]; sm[BA + tid] = b_alpha[tid];
        sm[BNM + tid] = bn_mean[tid];
        sm[BNR + tid] = rsqrtf(bn_var[tid] + 1e-5f);
        sm[BNG + tid] = bn_gamma[tid];
        sm[BNB + tid] = bn_beta[tid];
    }
    __syncthreads();

    int warp = tid >> 5, lane = tid & 31;
    int d0 = warp * 4;

    for (int g = blockIdx.x; g < B_ * S_; g += gridDim.x) {
        const float* gp = g_groups + (size_t)g * 96;
        float gc0 = __ldg(gp + lane);
        float gc1 = __ldg(gp + 32 + lane);
        float gc2 = __ldg(gp + 64 + lane);

        // h = gelu(BN(W_alpha @ g + b_alpha))
#pragma unroll
        for (int r = 0; r < 4; ++r) {
            int d = d0 + r;
            float hv = sm[WA + d] * gc0 + sm[WA + 64 + d] * gc1 +
                       sm[WA + 128 + d] * gc2 + sm[BA + d];
            hv = ((hv - sm[BNM + d]) * sm[BNR + d]) * sm[BNG + d] + sm[BNB + d];
            hv = gelu_exact(hv);
            sm[Hb + d * 32 + lane] = hv;
        }
        __syncthreads();

        // Q, K, V (fused loop)
        {
            float aq[4] = {0, 0, 0, 0}, ak[4] = {0, 0, 0, 0}, av[4] = {0, 0, 0, 0};
#pragma unroll 8
            for (int c = 0; c < 64; ++c) {
                float hvv = sm[Hb + c * 32 + lane];
                float4 wq4 = *(const float4*)&sm[WQ + c * 64 + d0];
                float4 wk4 = *(const float4*)&sm[WK + c * 64 + d0];
                float4 wv4 = *(const float4*)&sm[WV + c * 64 + d0];
                aq[0] += wq4.x * hvv; aq[1] += wq4.y * hvv;
                aq[2] += wq4.z * hvv; aq[3] += wq4.w * hvv;
                ak[0] += wk4.x * hvv; ak[1] += wk4.y * hvv;
                ak[2] += wk4.z * hvv; ak[3] += wk4.w * hvv;
                av[0] += wv4.x * hvv; av[1] += wv4.y * hvv;
                av[2] += wv4.z * hvv; av[3] += wv4.w * hvv;
            }
#pragma unroll
            for (int r = 0; r < 4; ++r) {
                int d = d0 + r;
                sm[Qb + d * 32 + lane] = aq[r] + sm[BQ + d];
                sm[Kb + d * 32 + lane] = ak[r] + sm[BK + d];
                sm[Vb + d * 32 + lane] = av[r] + sm[BV + d];
            }
        }
        __syncthreads();

        // attention logits: warp owns rows i=warp and i=warp+16, lane = j
        {
            float a0 = 0.f, a1 = 0.f;
#pragma unroll 8
            for (int dd = 0; dd < 64; ++dd) {
                float kv = sm[Kb + dd * 32 + lane];
                a0 += sm[Qb + dd * 32 + warp] * kv;
                a1 += sm[Qb + dd * 32 + warp + 16] * kv;
            }
            a0 *= 0.125f; a1 *= 0.125f;
            float m0 = a0, m1 = a1;
#pragma unroll
            for (int off = 16; off; off >>= 1) {
                m0 = fmaxf(m0, __shfl_xor_sync(FULLMASK, m0, off));
                m1 = fmaxf(m1, __shfl_xor_sync(FULLMASK, m1, off));
            }
            float e0 = expf(a0 - m0), e1 = expf(a1 - m1);
            float s0 = e0, s1 = e1;
#pragma unroll
            for (int off = 16; off; off >>= 1) {
                s0 += __shfl_xor_sync(FULLMASK, s0, off);
                s1 += __shfl_xor_sync(FULLMASK, s1, off);
            }
            sm[ATT + warp * 33 + lane]        = e0 / s0;
            sm[ATT + (warp + 16) * 33 + lane] = e1 / s1;
        }
        __syncthreads();

        // res[d,i] = sum_j attn[i,j] v[d,j]; T = res + h overwrites Qb
        {
            float ar[4] = {0, 0, 0, 0};
#pragma unroll 8
            for (int j = 0; j < 32; ++j) {
                float ap = sm[ATT + lane * 33 + j];
                ar[0] += ap * sm[Vb + (d0 + 0) * 32 + j];
                ar[1] += ap * sm[Vb + (d0 + 1) * 32 + j];
                ar[2] += ap * sm[Vb + (d0 + 2) * 32 + j];
                ar[3] += ap * sm[Vb + (d0 + 3) * 32 + j];
            }
#pragma unroll
            for (int r = 0; r < 4; ++r) {
                int d = d0 + r;
                sm[RESb + d * 32 + lane] = ar[r];
                sm[Qb + d * 32 + lane] = ar[r] + sm[Hb + d * 32 + lane];
            }
        }
        __syncthreads();

        // G1 = gelu(W_g1 @ T + b_g1)  -> stored in Kb
        {
            float a5[4] = {0, 0, 0, 0};
#pragma unroll 8
            for (int c = 0; c < 64; ++c) {
                float tv = sm[Qb + c * 32 + lane];
                float4 w4 = *(const float4*)&sm[WG1 + c * 64 + d0];
                a5[0] += w4.x * tv; a5[1] += w4.y * tv;
                a5[2] += w4.z * tv; a5[3] += w4.w * tv;
            }
#pragma unroll
            for (int r = 0; r < 4; ++r) {
                int d = d0 + r;
                sm[Kb + d * 32 + lane] = gelu_exact(a5[r] + sm[BG1 + d]);
            }
        }
        __syncthreads();

        // out = W_g2 @ G1 + b_g2 + res ; patches = max over k
        {
            float a6[4] = {0, 0, 0, 0};
#pragma unroll 8
            for (int c = 0; c < 64; ++c) {
                float gv = sm[Kb + c * 32 + lane];
                float4 w4 = *(const float4*)&sm[WG2 + c * 64 + d0];
                a6[0] += w4.x * gv; a6[1] += w4.y * gv;
                a6[2] += w4.z * gv; a6[3] += w4.w * gv;
            }
#pragma unroll
            for (int r = 0; r < 4; ++r) {
                int d = d0 + r;
                float v = a6[r] + sm[BG2 + d] + sm[RESb + d * 32 + lane];
#pragma unroll
                for (int off = 16; off; off >>= 1)
                    v = fmaxf(v, __shfl_xor_sync(FULLMASK, v, off));
                if (lane == 0) out[(size_t)g * 67 + 3 + d] = v;
            }
        }
        __syncthreads();
    }
}

// ============================ launch ======================================
extern "C" void kernel_launch(void* const* d_in, const int* in_sizes, int n_in,
                              void* d_out, int out_size) {
    (void)in_sizes; (void)n_in; (void)out_size;
    const float* x        = (const float*)d_in[0];
    const float* w_alpha  = (const float*)d_in[1];
    const float* b_alpha  = (const float*)d_in[2];
    const float* bn_gamma = (const float*)d_in[3];
    const float* bn_beta  = (const float*)d_in[4];
    const float* bn_mean  = (const float*)d_in[5];
    const float* bn_var   = (const float*)d_in[6];
    const float* w_q      = (const float*)d_in[7];
    const float* b_q      = (const float*)d_in[8];
    const float* w_k      = (const float*)d_in[9];
    const float* b_k      = (const float*)d_in[10];
    const float* w_v      = (const float*)d_in[11];
    const float* b_v      = (const float*)d_in[12];
    const float* w_g1     = (const float*)d_in[13];
    const float* b_g1     = (const float*)d_in[14];
    const float* w_g2     = (const float*)d_in[15];
    const float* b_g2     = (const float*)d_in[16];
    float* out = (float*)d_out;

    cudaFuncSetAttribute(knn_kernel,
                         cudaFuncAttributeMaxDynamicSharedMemorySize, 65536);
    cudaFuncSetAttribute(group_kernel,
                         cudaFuncAttributeMaxDynamicSharedMemorySize, 130432);

    fps_kernel<<<B_, 512>>>(x, out);
    knn_kernel<<<B_ * 4, 512, 65536>>>(x);
    group_kernel<<<148, 512, 130432>>>(w_alpha, b_alpha, bn_gamma, bn_beta,
                                       bn_mean, bn_var, w_q, b_q, w_k, b_k,
                                       w_v, b_v, w_g1, b_g1, w_g2, b_g2, out);
}

// round 3
// speedup vs baseline: 1.1365x; 1.1365x over previous
#include <cuda_runtime.h>
#include <math.h>

#define B_   32
#define N_   4096
#define S_   512
#define FULLMASK 0xffffffffu

// ---------------- device scratch (static, allocation-free) ----------------
__device__ float g_centroid[B_ * S_ * 3];
__device__ float g_groups[B_ * S_ * 96];   // [bs][c][k]

// ---------------- packed fp32x2 helpers (sm_100 native) -------------------
__device__ __forceinline__ unsigned long long pk2(float lo, float hi) {
    unsigned long long r;
    asm("mov.b64 %0, {%1, %2};" : "=l"(r) : "f"(lo), "f"(hi));
    return r;
}
__device__ __forceinline__ void upk2(unsigned long long v, float& lo, float& hi) {
    asm("mov.b64 {%0, %1}, %2;" : "=f"(lo), "=f"(hi) : "l"(v));
}
__device__ __forceinline__ unsigned long long fma2_(unsigned long long a,
                                                   unsigned long long b,
                                                   unsigned long long c) {
    unsigned long long d;
    asm("fma.rn.f32x2 %0, %1, %2, %3;" : "=l"(d) : "l"(a), "l"(b), "l"(c));
    return d;
}

// ============================ FPS =========================================
// one block per batch; x staged in smem; REDUX argmax; 1 barrier per step
__global__ __launch_bounds__(512) void fps_kernel(const float* __restrict__ x,
                                                  float* __restrict__ out) {
    extern __shared__ float smf[];
    float* sx0 = smf;
    float* sx1 = smf + 4096;
    float* sx2 = smf + 8192;
    unsigned long long* pb = (unsigned long long*)(smf + 12288); // 2 x 16 keys

    int b = blockIdx.x, tid = threadIdx.x;
    int lane = tid & 31, warp = tid >> 5;
    const float* xb = x + (size_t)b * N_ * 3;

    float px[8], py[8], pz[8], dist[8];
#pragma unroll
    for (int i = 0; i < 8; ++i) {
        int n = tid + i * 512;
        float a0 = xb[n * 3 + 0], a1 = xb[n * 3 + 1], a2 = xb[n * 3 + 2];
        px[i] = a0; py[i] = a1; pz[i] = a2;
        sx0[n] = a0; sx1[n] = a1; sx2[n] = a2;
        dist[i] = 1e10f;
    }
    __syncthreads();

    int last = 0;
    for (int s = 0; s < S_; ++s) {
        float c0 = sx0[last], c1 = sx1[last], c2 = sx2[last];
        if (tid == 0) {
            int bs = b * S_ + s;
            out[(size_t)bs * 67 + 0] = c0;
            out[(size_t)bs * 67 + 1] = c1;
            out[(size_t)bs * 67 + 2] = c2;
            g_centroid[bs * 3 + 0] = c0;
            g_centroid[bs * 3 + 1] = c1;
            g_centroid[bs * 3 + 2] = c2;
        }
#pragma unroll
        for (int i = 0; i < 8; ++i) {
            float dx = px[i] - c0, dy = py[i] - c1, dz = pz[i] - c2;
            float d = (dx * dx + dy * dy) + dz * dz;
            dist[i] = fminf(dist[i], d);
        }
        float bv = dist[0];
#pragma unroll
        for (int i = 1; i < 8; ++i) bv = fmaxf(bv, dist[i]);
        unsigned vb = __float_as_uint(bv);          // dist >= 0: order-preserving
        unsigned bi = 0xffffffffu;
#pragma unroll
        for (int i = 0; i < 8; ++i)
            if (__float_as_uint(dist[i]) == vb)
                bi = min(bi, (unsigned)(tid + i * 512));

        unsigned wmax = __reduce_max_sync(FULLMASK, vb);
        unsigned cand = (vb == wmax) ? bi : 0xffffffffu;
        unsigned widx = __reduce_min_sync(FULLMASK, cand);
        int par = s & 1;
        if (lane == 0)
            pb[par * 16 + warp] =
                ((unsigned long long)wmax << 32) |
                (unsigned long long)(0xffffffffu - widx);
        __syncthreads();
        unsigned long long best = 0;
#pragma unroll
        for (int w = 0; w < 16; ++w) {
            unsigned long long k = pb[par * 16 + w];
            best = (k > best) ? k : best;
        }
        last = (int)(0xffffffffu - (unsigned)best);
    }
}

// ============================ KNN top-32 ==================================
__global__ __launch_bounds__(512) void knn_kernel(const float* __restrict__ x) {
    int b    = blockIdx.x >> 2;
    int part = blockIdx.x & 3;
    extern __shared__ float smk[];
    float* sx0 = smk;
    float* sx1 = smk + 4096;
    float* sx2 = smk + 8192;
    float* sxs = smk + 12288;

    const float* xb = x + (size_t)b * N_ * 3;
    for (int i = threadIdx.x; i < N_; i += 512) {
        float a0 = xb[i * 3 + 0], a1 = xb[i * 3 + 1], a2 = xb[i * 3 + 2];
        sx0[i] = a0; sx1[i] = a1; sx2[i] = a2;
        sxs[i] = (a0 * a0 + a1 * a1) + a2 * a2;
    }
    __syncthreads();

    int warp = threadIdx.x >> 5, lane = threadIdx.x & 31;
    for (int j = 0; j < 8; ++j) {
        int s  = part * 128 + j * 16 + warp;
        int bs = b * S_ + s;
        float c0 = g_centroid[bs * 3 + 0];
        float c1 = g_centroid[bs * 3 + 1];
        float c2 = g_centroid[bs * 3 + 2];
        float cs = (c0 * c0 + c1 * c1) + c2 * c2;

        float lv = 3.402823466e38f;
        int   li = -1;
        for (int base = 0; base < N_; base += 32) {
            int n = base + lane;
            float dot = (c0 * sx0[n] + c1 * sx1[n]) + c2 * sx2[n];
            float d2  = (cs + sxs[n]) - 2.0f * dot;
            float thr = __shfl_sync(FULLMASK, lv, 31);
            unsigned m = __ballot_sync(FULLMASK, d2 < thr);
            while (m) {
                int src = __ffs(m) - 1;
                m &= m - 1;
                float cd = __shfl_sync(FULLMASK, d2, src);
                int   cn = base + src;
                thr = __shfl_sync(FULLMASK, lv, 31);
                if (cd < thr) {
                    unsigned keep = __ballot_sync(FULLMASK,
                        (lv < cd) || (lv == cd && li < cn));
                    int pos = __popc(keep);
                    float pv = __shfl_up_sync(FULLMASK, lv, 1);
                    int   pi = __shfl_up_sync(FULLMASK, li, 1);
                    if (lane == pos)      { lv = cd; li = cn; }
                    else if (lane > pos)  { lv = pv; li = pi; }
                }
            }
        }
        float gx = sx0[li] - c0, gy = sx1[li] - c1, gz = sx2[li] - c2;
        float* gp = g_groups + (size_t)bs * 96;
        gp[lane]      = gx;
        gp[32 + lane] = gy;
        gp[64 + lane] = gz;
    }
}

// ======================= per-group dense compute ==========================
__device__ __forceinline__ float gelu_exact(float v) {
    return 0.5f * v * (1.0f + erff(v * 0.70710678118654752440f));
}

// smem float-offsets
#define WU_   0
#define WV_   4096
#define WG1_  8192
#define WG2_  12288
#define WA_   16384
#define WQKB_ 16576
#define BV_   16704
#define BG1_  16768
#define BG2_  16832
#define BA_   16896
#define BNM_  16960
#define BNR_  17024
#define BNG_  17088
#define BNB_  17152
#define CB_   17216
#define Hb_   17232
#define Ub_   19280
#define VbT_  21328
#define RESb_ 23504
#define ATT_  25552
#define RBs_  26608
#define CAs_  26640
#define Hp_   26672
#define SMTOT 28720   // floats -> 114880 bytes

__global__ __launch_bounds__(512) void group_kernel(
    const float* __restrict__ w_alpha, const float* __restrict__ b_alpha,
    const float* __restrict__ bn_gamma, const float* __restrict__ bn_beta,
    const float* __restrict__ bn_mean,  const float* __restrict__ bn_var,
    const float* __restrict__ w_q, const float* __restrict__ b_q,
    const float* __restrict__ w_k, const float* __restrict__ b_k,
    const float* __restrict__ w_v, const float* __restrict__ b_v,
    const float* __restrict__ w_g1, const float* __restrict__ b_g1,
    const float* __restrict__ w_g2, const float* __restrict__ b_g2,
    float* __restrict__ out) {
    extern __shared__ float sm[];
    int tid = threadIdx.x;
    int warp = tid >> 5, lane = tid & 31;
    int d0 = warp * 4;

    // ---------- phase 1: raw staging ----------
    for (int i = tid; i < 4096; i += 512) {
        int d = i >> 6, c = i & 63;
        sm[WV_  + c * 64 + d] = w_v[i];
        sm[WG1_ + c * 64 + d] = w_g1[i];
        sm[WG2_ + c * 64 + d] = w_g2[i];
        sm[Hb_  + i] = w_q[i];   // scratch: raw wq [d*64+c]
        sm[VbT_ + i] = w_k[i];   // scratch: raw wk [d*64+c]
    }
    if (tid < 192) { int d = tid / 3, c = tid % 3; sm[WA_ + c * 64 + d] = w_alpha[tid]; }
    if (tid < 64) {
        sm[BV_ + tid] = b_v[tid];
        sm[BG1_ + tid] = b_g1[tid]; sm[BG2_ + tid] = b_g2[tid];
        sm[BA_ + tid] = b_alpha[tid];
        sm[BNM_ + tid] = bn_mean[tid];
        sm[BNR_ + tid] = rsqrtf(bn_var[tid] + 1e-5f);
        sm[BNG_ + tid] = bn_gamma[tid];
        sm[BNB_ + tid] = bn_beta[tid];
    }
    __syncthreads();

    // ---------- phase 2: P = Wq^T Wk, folded bias vectors ----------
    for (int i = tid; i < 4096; i += 512) {
        int c = i & 63, cc = i >> 6;
        float s = 0.f;
#pragma unroll 8
        for (int d = 0; d < 64; ++d)
            s += sm[Hb_ + d * 64 + c] * sm[VbT_ + d * 64 + cc];
        sm[WU_ + cc * 64 + c] = s;     // P[c,cc] stored contraction-major
    }
    if (tid < 64) {
        int c = tid;
        float aq = 0.f, ak = 0.f;
#pragma unroll 8
        for (int d = 0; d < 64; ++d) {
            aq += sm[Hb_ + d * 64 + c] * b_k[d];   // wqb = Wq^T b_k
            ak += sm[VbT_ + d * 64 + c] * b_q[d];  // wkb = Wk^T b_q
        }
        sm[WQKB_ + 2 * c]     = ak;
        sm[WQKB_ + 2 * c + 1] = aq;
    }
    if (tid == 511) {
        float s = 0.f;
        for (int d = 0; d < 64; ++d) s += b_q[d] * b_k[d];
        sm[CB_] = s;
    }
    __syncthreads();

    // ---------- main per-group loop ----------
    for (int g = blockIdx.x; g < B_ * S_; g += gridDim.x) {
        const float* gp = g_groups + (size_t)g * 96;
        float gc0 = __ldg(gp + lane);
        float gc1 = __ldg(gp + 32 + lane);
        float gc2 = __ldg(gp + 64 + lane);

        // A: h = gelu(BN(W_alpha g + b_alpha));  also packed H rows
#pragma unroll
        for (int r = 0; r < 4; ++r) {
            int d = d0 + r;
            float hv = sm[WA_ + d] * gc0 + sm[WA_ + 64 + d] * gc1 +
                       sm[WA_ + 128 + d] * gc2 + sm[BA_ + d];
            hv = ((hv - sm[BNM_ + d]) * sm[BNR_ + d]) * sm[BNG_ + d] + sm[BNB_ + d];
            hv = gelu_exact(hv);
            sm[Hb_ + d * 32 + lane] = hv;
            float hv_hi = __shfl_down_sync(FULLMASK, hv, 16);
            if (lane < 16)
                *(unsigned long long*)&sm[Hp_ + (d * 16 + lane) * 2] = pk2(hv, hv_hi);
        }
        __syncthreads();

        // B: u = P h ; v = Wv h + bv (stored transposed)
        {
            unsigned long long u01 = 0, u23 = 0, v01 = 0, v23 = 0;
#pragma unroll 8
            for (int cc = 0; cc < 64; ++cc) {
                float hv = sm[Hb_ + cc * 32 + lane];
                unsigned long long hh = pk2(hv, hv);
                ulonglong2 wu = *reinterpret_cast<const ulonglong2*>(&sm[WU_ + cc * 64 + d0]);
                u01 = fma2_(wu.x, hh, u01); u23 = fma2_(wu.y, hh, u23);
                ulonglong2 wv = *reinterpret_cast<const ulonglong2*>(&sm[WV_ + cc * 64 + d0]);
                v01 = fma2_(wv.x, hh, v01); v23 = fma2_(wv.y, hh, v23);
            }
            float u0, u1, u2, u3, v0, v1, v2, v3;
            upk2(u01, u0, u1); upk2(u23, u2, u3);
            upk2(v01, v0, v1); upk2(v23, v2, v3);
            sm[Ub_ + (d0 + 0) * 32 + lane] = u0;
            sm[Ub_ + (d0 + 1) * 32 + lane] = u1;
            sm[Ub_ + (d0 + 2) * 32 + lane] = u2;
            sm[Ub_ + (d0 + 3) * 32 + lane] = u3;
            float4 vv;
            vv.x = v0 + sm[BV_ + d0 + 0];
            vv.y = v1 + sm[BV_ + d0 + 1];
            vv.z = v2 + sm[BV_ + d0 + 2];
            vv.w = v3 + sm[BV_ + d0 + 3];
            *reinterpret_cast<float4*>(&sm[VbT_ + lane * 68 + d0]) = vv;
        }
        if (warp == 0) {   // bias dot-products rB[j], cA[i]
            unsigned long long rc = 0;
#pragma unroll 8
            for (int cc = 0; cc < 64; ++cc) {
                float hv = sm[Hb_ + cc * 32 + lane];
                rc = fma2_(*(const unsigned long long*)&sm[WQKB_ + 2 * cc],
                           pk2(hv, hv), rc);
            }
            float rB, cA;
            upk2(rc, rB, cA);
            sm[RBs_ + lane] = rB;
            sm[CAs_ + lane] = cA;
        }
        __syncthreads();

        // C: logits = h^T u + cA[i] + rB[j] + c0b ; softmax
        {
            float cb = sm[CB_];
            float base0 = sm[CAs_ + warp]      + sm[RBs_ + lane] + cb;
            float base1 = sm[CAs_ + warp + 16] + sm[RBs_ + lane] + cb;
            unsigned long long acc = pk2(base0, base1);
#pragma unroll 8
            for (int cc = 0; cc < 64; ++cc) {
                float uv = sm[Ub_ + cc * 32 + lane];
                unsigned long long hp =
                    *(const unsigned long long*)&sm[Hp_ + (cc * 16 + warp) * 2];
                acc = fma2_(hp, pk2(uv, uv), acc);
            }
            float a0, a1;
            upk2(acc, a0, a1);
            a0 *= 0.125f; a1 *= 0.125f;
            float m0 = a0, m1 = a1;
#pragma unroll
            for (int off = 16; off; off >>= 1) {
                m0 = fmaxf(m0, __shfl_xor_sync(FULLMASK, m0, off));
                m1 = fmaxf(m1, __shfl_xor_sync(FULLMASK, m1, off));
            }
            float e0 = expf(a0 - m0), e1 = expf(a1 - m1);
            float s0 = e0, s1 = e1;
#pragma unroll
            for (int off = 16; off; off >>= 1) {
                s0 += __shfl_xor_sync(FULLMASK, s0, off);
                s1 += __shfl_xor_sync(FULLMASK, s1, off);
            }
            sm[ATT_ + warp * 33 + lane]        = e0 / s0;
            sm[ATT_ + (warp + 16) * 33 + lane] = e1 / s1;
        }
        __syncthreads();

        // D: res = attn v^T ; T = res + h (in place over Hb)
        {
            unsigned long long r01 = 0, r23 = 0;
#pragma unroll 8
            for (int j = 0; j < 32; ++j) {
                float ap = sm[ATT_ + lane * 33 + j];
                unsigned long long aa = pk2(ap, ap);
                ulonglong2 vv = *reinterpret_cast<const ulonglong2*>(&sm[VbT_ + j * 68 + d0]);
                r01 = fma2_(vv.x, aa, r01); r23 = fma2_(vv.y, aa, r23);
            }
            float r0, r1, r2, r3;
            upk2(r01, r0, r1); upk2(r23, r2, r3);
            float ar[4] = {r0, r1, r2, r3};
#pragma unroll
            for (int r = 0; r < 4; ++r) {
                int d = d0 + r;
                sm[RESb_ + d * 32 + lane] = ar[r];
                sm[Hb_ + d * 32 + lane] += ar[r];   // T
            }
        }
        __syncthreads();

        // E: G1 = gelu(Wg1 T + bg1) -> Ub
        {
            unsigned long long a01 = 0, a23 = 0;
#pragma unroll 8
            for (int cc = 0; cc < 64; ++cc) {
                float tv = sm[Hb_ + cc * 32 + lane];
                unsigned long long hh = pk2(tv, tv);
                ulonglong2 w = *reinterpret_cast<const ulonglong2*>(&sm[WG1_ + cc * 64 + d0]);
                a01 = fma2_(w.x, hh, a01); a23 = fma2_(w.y, hh, a23);
            }
            float a0, a1, a2, a3;
            upk2(a01, a0, a1); upk2(a23, a2, a3);
            sm[Ub_ + (d0 + 0) * 32 + lane] = gelu_exact(a0 + sm[BG1_ + d0 + 0]);
            sm[Ub_ + (d0 + 1) * 32 + lane] = gelu_exact(a1 + sm[BG1_ + d0 + 1]);
            sm[Ub_ + (d0 + 2) * 32 + lane] = gelu_exact(a2 + sm[BG1_ + d0 + 2]);
            sm[Ub_ + (d0 + 3) * 32 + lane] = gelu_exact(a3 + sm[BG1_ + d0 + 3]);
        }
        __syncthreads();

        // F: out = Wg2 G1 + bg2 + res ; max over k
        {
            unsigned long long a01 = 0, a23 = 0;
#pragma unroll 8
            for (int cc = 0; cc < 64; ++cc) {
                float gv = sm[Ub_ + cc * 32 + lane];
                unsigned long long hh = pk2(gv, gv);
                ulonglong2 w = *reinterpret_cast<const ulonglong2*>(&sm[WG2_ + cc * 64 + d0]);
                a01 = fma2_(w.x, hh, a01); a23 = fma2_(w.y, hh, a23);
            }
            float a0, a1, a2, a3;
            upk2(a01, a0, a1); upk2(a23, a2, a3);
            float av[4] = {a0, a1, a2, a3};
#pragma unroll
            for (int r = 0; r < 4; ++r) {
                int d = d0 + r;
                float v = av[r] + sm[BG2_ + d] + sm[RESb_ + d * 32 + lane];
#pragma unroll
                for (int off = 16; off; off >>= 1)
                    v = fmaxf(v, __shfl_xor_sync(FULLMASK, v, off));
                if (lane == 0) out[(size_t)g * 67 + 3 + d] = v;
            }
        }
        __syncthreads();
    }
}

// ============================ launch ======================================
extern "C" void kernel_launch(void* const* d_in, const int* in_sizes, int n_in,
                              void* d_out, int out_size) {
    (void)in_sizes; (void)n_in; (void)out_size;
    const float* x        = (const float*)d_in[0];
    const float* w_alpha  = (const float*)d_in[1];
    const float* b_alpha  = (const float*)d_in[2];
    const float* bn_gamma = (const float*)d_in[3];
    const float* bn_beta  = (const float*)d_in[4];
    const float* bn_mean  = (const float*)d_in[5];
    const float* bn_var   = (const float*)d_in[6];
    const float* w_q      = (const float*)d_in[7];
    const float* b_q      = (const float*)d_in[8];
    const float* w_k      = (const float*)d_in[9];
    const float* b_k      = (const float*)d_in[10];
    const float* w_v      = (const float*)d_in[11];
    const float* b_v      = (const float*)d_in[12];
    const float* w_g1     = (const float*)d_in[13];
    const float* b_g1     = (const float*)d_in[14];
    const float* w_g2     = (const float*)d_in[15];
    const float* b_g2     = (const float*)d_in[16];
    float* out = (float*)d_out;

    cudaFuncSetAttribute(fps_kernel,
                         cudaFuncAttributeMaxDynamicSharedMemorySize, 49664);
    cudaFuncSetAttribute(knn_kernel,
                         cudaFuncAttributeMaxDynamicSharedMemorySize, 65536);
    cudaFuncSetAttribute(group_kernel,
                         cudaFuncAttributeMaxDynamicSharedMemorySize, SMTOT * 4);

    fps_kernel<<<B_, 512, 49664>>>(x, out);
    knn_kernel<<<B_ * 4, 512, 65536>>>(x);
    group_kernel<<<148, 512, SMTOT * 4>>>(w_alpha, b_alpha, bn_gamma, bn_beta,
                                          bn_mean, bn_var, w_q, b_q, w_k, b_k,
                                          w_v, b_v, w_g1, b_g1, w_g2, b_g2, out);
}

// round 4
// speedup vs baseline: 1.1400x; 1.0030x over previous
#include <cuda_runtime.h>
#include <math.h>

#define B_   32
#define N_   4096
#define S_   512
#define FULLMASK 0xffffffffu

// ---------------- device scratch (static, allocation-free) ----------------
__device__ float g_centroid[B_ * S_ * 3];
__device__ float g_groups[B_ * S_ * 96];   // [bs][c][k]

// ---------------- packed fp32x2 helpers (sm_100 native) -------------------
__device__ __forceinline__ unsigned long long pk2(float lo, float hi) {
    unsigned long long r;
    asm("mov.b64 %0, {%1, %2};" : "=l"(r) : "f"(lo), "f"(hi));
    return r;
}
__device__ __forceinline__ void upk2(unsigned long long v, float& lo, float& hi) {
    asm("mov.b64 {%0, %1}, %2;" : "=f"(lo), "=f"(hi) : "l"(v));
}
__device__ __forceinline__ unsigned long long fma2_(unsigned long long a,
                                                   unsigned long long b,
                                                   unsigned long long c) {
    unsigned long long d;
    asm("fma.rn.f32x2 %0, %1, %2, %3;" : "=l"(d) : "l"(a), "l"(b), "l"(c));
    return d;
}

// ============================ FPS =========================================
// one block per batch; x staged in smem; REDUX argmax; 1 barrier per step
__global__ __launch_bounds__(512) void fps_kernel(const float* __restrict__ x,
                                                  float* __restrict__ out) {
    extern __shared__ float smf[];
    float* sx0 = smf;
    float* sx1 = smf + 4096;
    float* sx2 = smf + 8192;
    unsigned long long* pb = (unsigned long long*)(smf + 12288); // 2 x 16 keys

    int b = blockIdx.x, tid = threadIdx.x;
    int lane = tid & 31, warp = tid >> 5;
    const float* xb = x + (size_t)b * N_ * 3;

    float px[8], py[8], pz[8], dist[8];
#pragma unroll
    for (int i = 0; i < 8; ++i) {
        int n = tid + i * 512;
        float a0 = xb[n * 3 + 0], a1 = xb[n * 3 + 1], a2 = xb[n * 3 + 2];
        px[i] = a0; py[i] = a1; pz[i] = a2;
        sx0[n] = a0; sx1[n] = a1; sx2[n] = a2;
        dist[i] = 1e10f;
    }
    __syncthreads();

    int last = 0;
    for (int s = 0; s < S_; ++s) {
        float c0 = sx0[last], c1 = sx1[last], c2 = sx2[last];
        if (tid == 0) {
            int bs = b * S_ + s;
            out[(size_t)bs * 67 + 0] = c0;
            out[(size_t)bs * 67 + 1] = c1;
            out[(size_t)bs * 67 + 2] = c2;
            g_centroid[bs * 3 + 0] = c0;
            g_centroid[bs * 3 + 1] = c1;
            g_centroid[bs * 3 + 2] = c2;
        }
#pragma unroll
        for (int i = 0; i < 8; ++i) {
            float dx = px[i] - c0, dy = py[i] - c1, dz = pz[i] - c2;
            float d = (dx * dx + dy * dy) + dz * dz;
            dist[i] = fminf(dist[i], d);
        }
        float bv = dist[0];
#pragma unroll
        for (int i = 1; i < 8; ++i) bv = fmaxf(bv, dist[i]);
        unsigned vb = __float_as_uint(bv);          // dist >= 0: order-preserving
        unsigned bi = 0xffffffffu;
#pragma unroll
        for (int i = 0; i < 8; ++i)
            if (__float_as_uint(dist[i]) == vb)
                bi = min(bi, (unsigned)(tid + i * 512));

        unsigned wmax = __reduce_max_sync(FULLMASK, vb);
        unsigned cand = (vb == wmax) ? bi : 0xffffffffu;
        unsigned widx = __reduce_min_sync(FULLMASK, cand);
        int par = s & 1;
        if (lane == 0)
            pb[par * 16 + warp] =
                ((unsigned long long)wmax << 32) |
                (unsigned long long)(0xffffffffu - widx);
        __syncthreads();
        unsigned long long best = 0;
#pragma unroll
        for (int w = 0; w < 16; ++w) {
            unsigned long long k = pb[par * 16 + w];
            best = (k > best) ? k : best;
        }
        last = (int)(0xffffffffu - (unsigned)best);
    }
}

// ============================ KNN top-32 ==================================
__global__ __launch_bounds__(512) void knn_kernel(const float* __restrict__ x) {
    int b    = blockIdx.x >> 2;
    int part = blockIdx.x & 3;
    extern __shared__ float smk[];
    float* sx0 = smk;
    float* sx1 = smk + 4096;
    float* sx2 = smk + 8192;
    float* sxs = smk + 12288;

    const float* xb = x + (size_t)b * N_ * 3;
    for (int i = threadIdx.x; i < N_; i += 512) {
        float a0 = xb[i * 3 + 0], a1 = xb[i * 3 + 1], a2 = xb[i * 3 + 2];
        sx0[i] = a0; sx1[i] = a1; sx2[i] = a2;
        sxs[i] = (a0 * a0 + a1 * a1) + a2 * a2;
    }
    __syncthreads();

    int warp = threadIdx.x >> 5, lane = threadIdx.x & 31;
    for (int j = 0; j < 8; ++j) {
        int s  = part * 128 + j * 16 + warp;
        int bs = b * S_ + s;
        float c0 = g_centroid[bs * 3 + 0];
        float c1 = g_centroid[bs * 3 + 1];
        float c2 = g_centroid[bs * 3 + 2];
        float cs = (c0 * c0 + c1 * c1) + c2 * c2;

        float lv = 3.402823466e38f;
        int   li = -1;
        for (int base = 0; base < N_; base += 32) {
            int n = base + lane;
            float dot = (c0 * sx0[n] + c1 * sx1[n]) + c2 * sx2[n];
            float d2  = (cs + sxs[n]) - 2.0f * dot;
            float thr = __shfl_sync(FULLMASK, lv, 31);
            unsigned m = __ballot_sync(FULLMASK, d2 < thr);
            while (m) {
                int src = __ffs(m) - 1;
                m &= m - 1;
                float cd = __shfl_sync(FULLMASK, d2, src);
                int   cn = base + src;
                thr = __shfl_sync(FULLMASK, lv, 31);
                if (cd < thr) {
                    unsigned keep = __ballot_sync(FULLMASK,
                        (lv < cd) || (lv == cd && li < cn));
                    int pos = __popc(keep);
                    float pv = __shfl_up_sync(FULLMASK, lv, 1);
                    int   pi = __shfl_up_sync(FULLMASK, li, 1);
                    if (lane == pos)      { lv = cd; li = cn; }
                    else if (lane > pos)  { lv = pv; li = pi; }
                }
            }
        }
        float gx = sx0[li] - c0, gy = sx1[li] - c1, gz = sx2[li] - c2;
        float* gp = g_groups + (size_t)bs * 96;
        gp[lane]      = gx;
        gp[32 + lane] = gy;
        gp[64 + lane] = gz;
    }
}

// ======================= per-group dense compute ==========================
__device__ __forceinline__ float gelu_exact(float v) {
    return 0.5f * v * (1.0f + erff(v * 0.70710678118654752440f));
}

// smem float-offsets
#define WU_   0
#define WV_   4096
#define WG1_  8192
#define WG2_  12288
#define WA_   16384
#define WQKB_ 16576
#define BV_   16704
#define BG1_  16768
#define BG2_  16832
#define BA_   16896
#define BNM_  16960
#define BNR_  17024
#define BNG_  17088
#define BNB_  17152
#define CB_   17216
#define Hb_   17232
#define Ub_   19280
#define VbT_  21328
#define RESb_ 23504
#define ATT_  25552
#define RBs_  26608
#define CAs_  26640
#define Hp_   26672
#define SMTOT 28720   // floats -> 114880 bytes

__global__ __launch_bounds__(512) void group_kernel(
    const float* __restrict__ w_alpha, const float* __restrict__ b_alpha,
    const float* __restrict__ bn_gamma, const float* __restrict__ bn_beta,
    const float* __restrict__ bn_mean,  const float* __restrict__ bn_var,
    const float* __restrict__ w_q, const float* __restrict__ b_q,
    const float* __restrict__ w_k, const float* __restrict__ b_k,
    const float* __restrict__ w_v, const float* __restrict__ b_v,
    const float* __restrict__ w_g1, const float* __restrict__ b_g1,
    const float* __restrict__ w_g2, const float* __restrict__ b_g2,
    float* __restrict__ out) {
    extern __shared__ float sm[];
    int tid = threadIdx.x;
    int warp = tid >> 5, lane = tid & 31;
    int d0 = warp * 4;

    // ---------- phase 1: raw staging ----------
    for (int i = tid; i < 4096; i += 512) {
        int d = i >> 6, c = i & 63;
        sm[WV_  + c * 64 + d] = w_v[i];
        sm[WG1_ + c * 64 + d] = w_g1[i];
        sm[WG2_ + c * 64 + d] = w_g2[i];
        sm[Hb_  + i] = w_q[i];   // scratch: raw wq [d*64+c]
        sm[VbT_ + i] = w_k[i];   // scratch: raw wk [d*64+c]
    }
    if (tid < 192) { int d = tid / 3, c = tid % 3; sm[WA_ + c * 64 + d] = w_alpha[tid]; }
    if (tid < 64) {
        sm[BV_ + tid] = b_v[tid];
        sm[BG1_ + tid] = b_g1[tid]; sm[BG2_ + tid] = b_g2[tid];
        sm[BA_ + tid] = b_alpha[tid];
        sm[BNM_ + tid] = bn_mean[tid];
        sm[BNR_ + tid] = rsqrtf(bn_var[tid] + 1e-5f);
        sm[BNG_ + tid] = bn_gamma[tid];
        sm[BNB_ + tid] = bn_beta[tid];
    }
    __syncthreads();

    // ---------- phase 2: P = Wq^T Wk, folded bias vectors ----------
    for (int i = tid; i < 4096; i += 512) {
        int c = i & 63, cc = i >> 6;
        float s = 0.f;
#pragma unroll 8
        for (int d = 0; d < 64; ++d)
            s += sm[Hb_ + d * 64 + c] * sm[VbT_ + d * 64 + cc];
        sm[WU_ + cc * 64 + c] = s;     // P[c,cc] stored contraction-major
    }
    if (tid < 64) {
        int c = tid;
        float aq = 0.f, ak = 0.f;
#pragma unroll 8
        for (int d = 0; d < 64; ++d) {
            aq += sm[Hb_ + d * 64 + c] * b_k[d];   // wqb = Wq^T b_k
            ak += sm[VbT_ + d * 64 + c] * b_q[d];  // wkb = Wk^T b_q
        }
        sm[WQKB_ + 2 * c]     = ak;
        sm[WQKB_ + 2 * c + 1] = aq;
    }
    if (tid == 511) {
        float s = 0.f;
        for (int d = 0; d < 64; ++d) s += b_q[d] * b_k[d];
        sm[CB_] = s;
    }
    __syncthreads();

    // ---------- main per-group loop ----------
    for (int g = blockIdx.x; g < B_ * S_; g += gridDim.x) {
        const float* gp = g_groups + (size_t)g * 96;
        float gc0 = __ldg(gp + lane);
        float gc1 = __ldg(gp + 32 + lane);
        float gc2 = __ldg(gp + 64 + lane);

        // A: h = gelu(BN(W_alpha g + b_alpha));  also packed H rows
#pragma unroll
        for (int r = 0; r < 4; ++r) {
            int d = d0 + r;
            float hv = sm[WA_ + d] * gc0 + sm[WA_ + 64 + d] * gc1 +
                       sm[WA_ + 128 + d] * gc2 + sm[BA_ + d];
            hv = ((hv - sm[BNM_ + d]) * sm[BNR_ + d]) * sm[BNG_ + d] + sm[BNB_ + d];
            hv = gelu_exact(hv);
            sm[Hb_ + d * 32 + lane] = hv;
            float hv_hi = __shfl_down_sync(FULLMASK, hv, 16);
            if (lane < 16)
                *(unsigned long long*)&sm[Hp_ + (d * 16 + lane) * 2] = pk2(hv, hv_hi);
        }
        __syncthreads();

        // B: u = P h ; v = Wv h + bv (stored transposed)
        {
            unsigned long long u01 = 0, u23 = 0, v01 = 0, v23 = 0;
#pragma unroll 8
            for (int cc = 0; cc < 64; ++cc) {
                float hv = sm[Hb_ + cc * 32 + lane];
                unsigned long long hh = pk2(hv, hv);
                ulonglong2 wu = *reinterpret_cast<const ulonglong2*>(&sm[WU_ + cc * 64 + d0]);
                u01 = fma2_(wu.x, hh, u01); u23 = fma2_(wu.y, hh, u23);
                ulonglong2 wv = *reinterpret_cast<const ulonglong2*>(&sm[WV_ + cc * 64 + d0]);
                v01 = fma2_(wv.x, hh, v01); v23 = fma2_(wv.y, hh, v23);
            }
            float u0, u1, u2, u3, v0, v1, v2, v3;
            upk2(u01, u0, u1); upk2(u23, u2, u3);
            upk2(v01, v0, v1); upk2(v23, v2, v3);
            sm[Ub_ + (d0 + 0) * 32 + lane] = u0;
            sm[Ub_ + (d0 + 1) * 32 + lane] = u1;
            sm[Ub_ + (d0 + 2) * 32 + lane] = u2;
            sm[Ub_ + (d0 + 3) * 32 + lane] = u3;
            float4 vv;
            vv.x = v0 + sm[BV_ + d0 + 0];
            vv.y = v1 + sm[BV_ + d0 + 1];
            vv.z = v2 + sm[BV_ + d0 + 2];
            vv.w = v3 + sm[BV_ + d0 + 3];
            *reinterpret_cast<float4*>(&sm[VbT_ + lane * 68 + d0]) = vv;
        }
        if (warp == 0) {   // bias dot-products rB[j], cA[i]
            unsigned long long rc = 0;
#pragma unroll 8
            for (int cc = 0; cc < 64; ++cc) {
                float hv = sm[Hb_ + cc * 32 + lane];
                rc = fma2_(*(const unsigned long long*)&sm[WQKB_ + 2 * cc],
                           pk2(hv, hv), rc);
            }
            float rB, cA;
            upk2(rc, rB, cA);
            sm[RBs_ + lane] = rB;
            sm[CAs_ + lane] = cA;
        }
        __syncthreads();

        // C: logits = h^T u + cA[i] + rB[j] + c0b ; softmax
        {
            float cb = sm[CB_];
            float base0 = sm[CAs_ + warp]      + sm[RBs_ + lane] + cb;
            float base1 = sm[CAs_ + warp + 16] + sm[RBs_ + lane] + cb;
            unsigned long long acc = pk2(base0, base1);
#pragma unroll 8
            for (int cc = 0; cc < 64; ++cc) {
                float uv = sm[Ub_ + cc * 32 + lane];
                unsigned long long hp =
                    *(const unsigned long long*)&sm[Hp_ + (cc * 16 + warp) * 2];
                acc = fma2_(hp, pk2(uv, uv), acc);
            }
            float a0, a1;
            upk2(acc, a0, a1);
            a0 *= 0.125f; a1 *= 0.125f;
            float m0 = a0, m1 = a1;
#pragma unroll
            for (int off = 16; off; off >>= 1) {
                m0 = fmaxf(m0, __shfl_xor_sync(FULLMASK, m0, off));
                m1 = fmaxf(m1, __shfl_xor_sync(FULLMASK, m1, off));
            }
            float e0 = expf(a0 - m0), e1 = expf(a1 - m1);
            float s0 = e0, s1 = e1;
#pragma unroll
            for (int off = 16; off; off >>= 1) {
                s0 += __shfl_xor_sync(FULLMASK, s0, off);
                s1 += __shfl_xor_sync(FULLMASK, s1, off);
            }
            sm[ATT_ + warp * 33 + lane]        = e0 / s0;
            sm[ATT_ + (warp + 16) * 33 + lane] = e1 / s1;
        }
        __syncthreads();

        // D: res = attn v^T ; T = res + h (in place over Hb)
        {
            unsigned long long r01 = 0, r23 = 0;
#pragma unroll 8
            for (int j = 0; j < 32; ++j) {
                float ap = sm[ATT_ + lane * 33 + j];
                unsigned long long aa = pk2(ap, ap);
                ulonglong2 vv = *reinterpret_cast<const ulonglong2*>(&sm[VbT_ + j * 68 + d0]);
                r01 = fma2_(vv.x, aa, r01); r23 = fma2_(vv.y, aa, r23);
            }
            float r0, r1, r2, r3;
            upk2(r01, r0, r1); upk2(r23, r2, r3);
            float ar[4] = {r0, r1, r2, r3};
#pragma unroll
            for (int r = 0; r < 4; ++r) {
                int d = d0 + r;
                sm[RESb_ + d * 32 + lane] = ar[r];
                sm[Hb_ + d * 32 + lane] += ar[r];   // T
            }
        }
        __syncthreads();

        // E: G1 = gelu(Wg1 T + bg1) -> Ub
        {
            unsigned long long a01 = 0, a23 = 0;
#pragma unroll 8
            for (int cc = 0; cc < 64; ++cc) {
                float tv = sm[Hb_ + cc * 32 + lane];
                unsigned long long hh = pk2(tv, tv);
                ulonglong2 w = *reinterpret_cast<const ulonglong2*>(&sm[WG1_ + cc * 64 + d0]);
                a01 = fma2_(w.x, hh, a01); a23 = fma2_(w.y, hh, a23);
            }
            float a0, a1, a2, a3;
            upk2(a01, a0, a1); upk2(a23, a2, a3);
            sm[Ub_ + (d0 + 0) * 32 + lane] = gelu_exact(a0 + sm[BG1_ + d0 + 0]);
            sm[Ub_ + (d0 + 1) * 32 + lane] = gelu_exact(a1 + sm[BG1_ + d0 + 1]);
            sm[Ub_ + (d0 + 2) * 32 + lane] = gelu_exact(a2 + sm[BG1_ + d0 + 2]);
            sm[Ub_ + (d0 + 3) * 32 + lane] = gelu_exact(a3 + sm[BG1_ + d0 + 3]);
        }
        __syncthreads();

        // F: out = Wg2 G1 + bg2 + res ; max over k
        {
            unsigned long long a01 = 0, a23 = 0;
#pragma unroll 8
            for (int cc = 0; cc < 64; ++cc) {
                float gv = sm[Ub_ + cc * 32 + lane];
                unsigned long long hh = pk2(gv, gv);
                ulonglong2 w = *reinterpret_cast<const ulonglong2*>(&sm[WG2_ + cc * 64 + d0]);
                a01 = fma2_(w.x, hh, a01); a23 = fma2_(w.y, hh, a23);
            }
            float a0, a1, a2, a3;
            upk2(a01, a0, a1); upk2(a23, a2, a3);
            float av[4] = {a0, a1, a2, a3};
#pragma unroll
            for (int r = 0; r < 4; ++r) {
                int d = d0 + r;
                float v = av[r] + sm[BG2_ + d] + sm[RESb_ + d * 32 + lane];
#pragma unroll
                for (int off = 16; off; off >>= 1)
                    v = fmaxf(v, __shfl_xor_sync(FULLMASK, v, off));
                if (lane == 0) out[(size_t)g * 67 + 3 + d] = v;
            }
        }
        __syncthreads();
    }
}

// ============================ launch ======================================
extern "C" void kernel_launch(void* const* d_in, const int* in_sizes, int n_in,
                              void* d_out, int out_size) {
    (void)in_sizes; (void)n_in; (void)out_size;
    const float* x        = (const float*)d_in[0];
    const float* w_alpha  = (const float*)d_in[1];
    const float* b_alpha  = (const float*)d_in[2];
    const float* bn_gamma = (const float*)d_in[3];
    const float* bn_beta  = (const float*)d_in[4];
    const float* bn_mean  = (const float*)d_in[5];
    const float* bn_var   = (const float*)d_in[6];
    const float* w_q      = (const float*)d_in[7];
    const float* b_q      = (const float*)d_in[8];
    const float* w_k      = (const float*)d_in[9];
    const float* b_k      = (const float*)d_in[10];
    const float* w_v      = (const float*)d_in[11];
    const float* b_v      = (const float*)d_in[12];
    const float* w_g1     = (const float*)d_in[13];
    const float* b_g1     = (const float*)d_in[14];
    const float* w_g2     = (const float*)d_in[15];
    const float* b_g2     = (const float*)d_in[16];
    float* out = (float*)d_out;

    cudaFuncSetAttribute(fps_kernel,
                         cudaFuncAttributeMaxDynamicSharedMemorySize, 49664);
    cudaFuncSetAttribute(knn_kernel,
                         cudaFuncAttributeMaxDynamicSharedMemorySize, 65536);
    cudaFuncSetAttribute(group_kernel,
                         cudaFuncAttributeMaxDynamicSharedMemorySize, SMTOT * 4);

    fps_kernel<<<B_, 512, 49664>>>(x, out);
    knn_kernel<<<B_ * 4, 512, 65536>>>(x);
    group_kernel<<<148, 512, SMTOT * 4>>>(w_alpha, b_alpha, bn_gamma, bn_beta,
                                          bn_mean, bn_var, w_q, b_q, w_k, b_k,
                                          w_v, b_v, w_g1, b_g1, w_g2, b_g2, out);
}

// round 5
// speedup vs baseline: 1.3806x; 1.2111x over previous
#include <cuda_runtime.h>
#include <math.h>

#define B_   32
#define N_   4096
#define S_   512
#define FULLMASK 0xffffffffu

__device__ float g_centroid[B_ * S_ * 3];
__device__ float g_groups[B_ * S_ * 96];   // [bs][c][k]

// ---------------- helpers -------------------------------------------------
__device__ __forceinline__ unsigned long long pk2(float lo, float hi) {
    unsigned long long r;
    asm("mov.b64 %0, {%1, %2};" : "=l"(r) : "f"(lo), "f"(hi));
    return r;
}
__device__ __forceinline__ void upk2(unsigned long long v, float& lo, float& hi) {
    asm("mov.b64 {%0, %1}, %2;" : "=f"(lo), "=f"(hi) : "l"(v));
}
__device__ __forceinline__ unsigned long long fma2_(unsigned long long a,
                                                   unsigned long long b,
                                                   unsigned long long c) {
    unsigned long long d;
    asm("fma.rn.f32x2 %0, %1, %2, %3;" : "=l"(d) : "l"(a), "l"(b), "l"(c));
    return d;
}
__device__ __forceinline__ unsigned tf32u(float f) {
    unsigned r;
    asm("cvt.rna.tf32.f32 %0, %1;" : "=r"(r) : "f"(f));
    return r;
}
__device__ __forceinline__ void split32(float x, unsigned& b, unsigned& s) {
    b = tf32u(x);
    s = tf32u(x - __uint_as_float(b));
}
__device__ __forceinline__ void mma8(float* c, const unsigned* a,
                                     unsigned b0, unsigned b1) {
    asm("mma.sync.aligned.m16n8k8.row.col.f32.tf32.tf32.f32 "
        "{%0,%1,%2,%3},{%4,%5,%6,%7},{%8,%9},{%0,%1,%2,%3};"
        : "+f"(c[0]), "+f"(c[1]), "+f"(c[2]), "+f"(c[3])
        : "r"(a[0]), "r"(a[1]), "r"(a[2]), "r"(a[3]), "r"(b0), "r"(b1));
}
__device__ __forceinline__ float gelu_exact(float v) {
    return 0.5f * v * (1.0f + erff(v * 0.70710678118654752440f));
}

// ============================ FPS (unchanged) =============================
__global__ __launch_bounds__(512) void fps_kernel(const float* __restrict__ x,
                                                  float* __restrict__ out) {
    extern __shared__ float smf[];
    float* sx0 = smf;
    float* sx1 = smf + 4096;
    float* sx2 = smf + 8192;
    unsigned long long* pb = (unsigned long long*)(smf + 12288);

    int b = blockIdx.x, tid = threadIdx.x;
    int lane = tid & 31, warp = tid >> 5;
    const float* xb = x + (size_t)b * N_ * 3;

    float px[8], py[8], pz[8], dist[8];
#pragma unroll
    for (int i = 0; i < 8; ++i) {
        int n = tid + i * 512;
        float a0 = xb[n * 3 + 0], a1 = xb[n * 3 + 1], a2 = xb[n * 3 + 2];
        px[i] = a0; py[i] = a1; pz[i] = a2;
        sx0[n] = a0; sx1[n] = a1; sx2[n] = a2;
        dist[i] = 1e10f;
    }
    __syncthreads();

    int last = 0;
    for (int s = 0; s < S_; ++s) {
        float c0 = sx0[last], c1 = sx1[last], c2 = sx2[last];
        if (tid == 0) {
            int bs = b * S_ + s;
            out[(size_t)bs * 67 + 0] = c0;
            out[(size_t)bs * 67 + 1] = c1;
            out[(size_t)bs * 67 + 2] = c2;
            g_centroid[bs * 3 + 0] = c0;
            g_centroid[bs * 3 + 1] = c1;
            g_centroid[bs * 3 + 2] = c2;
        }
#pragma unroll
        for (int i = 0; i < 8; ++i) {
            float dx = px[i] - c0, dy = py[i] - c1, dz = pz[i] - c2;
            float d = (dx * dx + dy * dy) + dz * dz;
            dist[i] = fminf(dist[i], d);
        }
        float bv = dist[0];
#pragma unroll
        for (int i = 1; i < 8; ++i) bv = fmaxf(bv, dist[i]);
        unsigned vb = __float_as_uint(bv);
        unsigned bi = 0xffffffffu;
#pragma unroll
        for (int i = 0; i < 8; ++i)
            if (__float_as_uint(dist[i]) == vb)
                bi = min(bi, (unsigned)(tid + i * 512));

        unsigned wmax = __reduce_max_sync(FULLMASK, vb);
        unsigned cand = (vb == wmax) ? bi : 0xffffffffu;
        unsigned widx = __reduce_min_sync(FULLMASK, cand);
        int par = s & 1;
        if (lane == 0)
            pb[par * 16 + warp] =
                ((unsigned long long)wmax << 32) |
                (unsigned long long)(0xffffffffu - widx);
        __syncthreads();
        unsigned long long best = 0;
#pragma unroll
        for (int w = 0; w < 16; ++w) {
            unsigned long long k = pb[par * 16 + w];
            best = (k > best) ? k : best;
        }
        last = (int)(0xffffffffu - (unsigned)best);
    }
}

// ============================ KNN (2 centroids / warp) ====================
__global__ __launch_bounds__(512) void knn_kernel(const float* __restrict__ x) {
    int b    = blockIdx.x >> 2;
    int part = blockIdx.x & 3;
    extern __shared__ float smk[];
    float* sx0 = smk;
    float* sx1 = smk + 4096;
    float* sx2 = smk + 8192;
    float* sxs = smk + 12288;

    const float* xb = x + (size_t)b * N_ * 3;
    for (int i = threadIdx.x; i < N_; i += 512) {
        float a0 = xb[i * 3 + 0], a1 = xb[i * 3 + 1], a2 = xb[i * 3 + 2];
        sx0[i] = a0; sx1[i] = a1; sx2[i] = a2;
        sxs[i] = (a0 * a0 + a1 * a1) + a2 * a2;
    }
    __syncthreads();

    int warp = threadIdx.x >> 5, lane = threadIdx.x & 31;
    for (int jj = 0; jj < 4; ++jj) {
        int sA = part * 128 + jj * 32 + warp * 2;
        int bsA = b * S_ + sA, bsB = bsA + 1;
        float cA0 = g_centroid[bsA * 3 + 0], cA1 = g_centroid[bsA * 3 + 1],
              cA2 = g_centroid[bsA * 3 + 2];
        float cB0 = g_centroid[bsB * 3 + 0], cB1 = g_centroid[bsB * 3 + 1],
              cB2 = g_centroid[bsB * 3 + 2];
        float csA = (cA0 * cA0 + cA1 * cA1) + cA2 * cA2;
        float csB = (cB0 * cB0 + cB1 * cB1) + cB2 * cB2;

        float lvA = 3.402823466e38f, lvB = 3.402823466e38f;
        int   liA = -1, liB = -1;
        for (int base = 0; base < N_; base += 32) {
            int n = base + lane;
            float p0 = sx0[n], p1 = sx1[n], p2 = sx2[n], ps = sxs[n];
            float d2A = (csA + ps) - 2.0f * ((cA0 * p0 + cA1 * p1) + cA2 * p2);
            float d2B = (csB + ps) - 2.0f * ((cB0 * p0 + cB1 * p1) + cB2 * p2);

            float thr = __shfl_sync(FULLMASK, lvA, 31);
            unsigned m = __ballot_sync(FULLMASK, d2A < thr);
            while (m) {
                int src = __ffs(m) - 1;
                m &= m - 1;
                float cd = __shfl_sync(FULLMASK, d2A, src);
                int   cn = base + src;
                thr = __shfl_sync(FULLMASK, lvA, 31);
                if (cd < thr) {
                    unsigned keep = __ballot_sync(FULLMASK,
                        (lvA < cd) || (lvA == cd && liA < cn));
                    int pos = __popc(keep);
                    float pv = __shfl_up_sync(FULLMASK, lvA, 1);
                    int   pi = __shfl_up_sync(FULLMASK, liA, 1);
                    if (lane == pos)      { lvA = cd; liA = cn; }
                    else if (lane > pos)  { lvA = pv; liA = pi; }
                }
            }
            thr = __shfl_sync(FULLMASK, lvB, 31);
            m = __ballot_sync(FULLMASK, d2B < thr);
            while (m) {
                int src = __ffs(m) - 1;
                m &= m - 1;
                float cd = __shfl_sync(FULLMASK, d2B, src);
                int   cn = base + src;
                thr = __shfl_sync(FULLMASK, lvB, 31);
                if (cd < thr) {
                    unsigned keep = __ballot_sync(FULLMASK,
                        (lvB < cd) || (lvB == cd && liB < cn));
                    int pos = __popc(keep);
                    float pv = __shfl_up_sync(FULLMASK, lvB, 1);
                    int   pi = __shfl_up_sync(FULLMASK, liB, 1);
                    if (lane == pos)      { lvB = cd; liB = cn; }
                    else if (lane > pos)  { lvB = pv; liB = pi; }
                }
            }
        }
        float* gpA = g_groups + (size_t)bsA * 96;
        gpA[lane]      = sx0[liA] - cA0;
        gpA[32 + lane] = sx1[liA] - cA1;
        gpA[64 + lane] = sx2[liA] - cA2;
        float* gpB = g_groups + (size_t)bsB * 96;
        gpB[lane]      = sx0[liB] - cB0;
        gpB[32 + lane] = sx1[liB] - cB1;
        gpB[64 + lane] = sx2[liB] - cB2;
    }
}

// ======================= per-group compute (3xTF32 mma) ===================
// smem float offsets
#define PB_    0        // PB[cc][c]  stride 72 (P[c][cc])
#define WVT_   4608     // Wv^T[c][d] stride 72
#define WG1T_  9216
#define WG2T_  13824
#define WA_    18432
#define WQKB_  18624
#define BV_    18752
#define BG1_   18816
#define BG2_   18880
#define BA_    18944
#define BNM_   19008
#define BNR_   19072
#define BNG_   19136
#define BNB_   19200
#define CB_    19264
#define H32_   19268    // h fp32 [d][j] stride 33
#define HT_    21380    // h fp32 [j][d] stride 68  (A-operand)
#define U_     23556    // u fp32 [c][j] stride 72  (B-operand)
#define V_     28164    // v fp32 [j][d] stride 72  (B-operand)
#define LG_    30468    // logits [i][j] stride 33
#define ATT_   31524    // attn fp32 [i][j] stride 68 (A-operand)
#define T32_   33700    // T  [i][d] stride 68 (A-operand)
#define G132_  35876    // G1 [i][d] stride 68 (A-operand)
#define RES_   38052    // res [i][d] stride 68
#define RBs_   40228
#define CAs_   40260
#define MP_    40292
#define SMTOT  40420    // floats -> 161680 bytes

__global__ __launch_bounds__(512) void group_kernel(
    const float* __restrict__ w_alpha, const float* __restrict__ b_alpha,
    const float* __restrict__ bn_gamma, const float* __restrict__ bn_beta,
    const float* __restrict__ bn_mean,  const float* __restrict__ bn_var,
    const float* __restrict__ w_q, const float* __restrict__ b_q,
    const float* __restrict__ w_k, const float* __restrict__ b_k,
    const float* __restrict__ w_v, const float* __restrict__ b_v,
    const float* __restrict__ w_g1, const float* __restrict__ b_g1,
    const float* __restrict__ w_g2, const float* __restrict__ b_g2,
    float* __restrict__ out) {
    extern __shared__ float sm[];
    int tid = threadIdx.x;
    int warp = tid >> 5, lane = tid & 31;
    int qg = lane >> 2, t4 = lane & 3;

    // ---- init: weights transposed to [c][d] stride 72; wq/wk scratch ----
    for (int i = tid; i < 4096; i += 512) {
        int d = i >> 6, c = i & 63;
        sm[WVT_  + c * 72 + d] = w_v[i];
        sm[WG1T_ + c * 72 + d] = w_g1[i];
        sm[WG2T_ + c * 72 + d] = w_g2[i];
        sm[U_    + i] = w_q[i];        // scratch raw wq
        sm[G132_ + i] = w_k[i];        // scratch raw wk
    }
    if (tid < 192) { int d = tid / 3, c = tid % 3; sm[WA_ + c * 64 + d] = w_alpha[tid]; }
    if (tid < 64) {
        sm[BV_ + tid] = b_v[tid];
        sm[BG1_ + tid] = b_g1[tid]; sm[BG2_ + tid] = b_g2[tid];
        sm[BA_ + tid] = b_alpha[tid];
        sm[BNM_ + tid] = bn_mean[tid];
        sm[BNR_ + tid] = rsqrtf(bn_var[tid] + 1e-5f);
        sm[BNG_ + tid] = bn_gamma[tid];
        sm[BNB_ + tid] = bn_beta[tid];
    }
    __syncthreads();
    // PB[cc][c] = sum_d wq[d][c] * wk[d][cc]
    for (int i = tid; i < 4096; i += 512) {
        int c = i & 63, cc = i >> 6;
        float s = 0.f;
#pragma unroll 8
        for (int d = 0; d < 64; ++d)
            s += sm[U_ + d * 64 + c] * sm[G132_ + d * 64 + cc];
        sm[PB_ + cc * 72 + c] = s;
    }
    if (tid < 64) {
        int c = tid;
        float aq = 0.f, ak = 0.f;
#pragma unroll 8
        for (int d = 0; d < 64; ++d) {
            aq += sm[U_ + d * 64 + c] * b_k[d];      // Wq^T b_k
            ak += sm[G132_ + d * 64 + c] * b_q[d];   // Wk^T b_q
        }
        sm[WQKB_ + 2 * c]     = ak;
        sm[WQKB_ + 2 * c + 1] = aq;
    }
    if (tid == 511) {
        float s = 0.f;
        for (int d = 0; d < 64; ++d) s += b_q[d] * b_k[d];
        sm[CB_] = s;
    }
    __syncthreads();

    int mt = warp >> 3, nt = warp & 7;       // 2 x 8 tiling (stages B,D,E,F)
    int d0 = warp * 4;

    for (int g = blockIdx.x; g < B_ * S_; g += gridDim.x) {
        const float* gp = g_groups + (size_t)g * 96;
        float gc0 = __ldg(gp + lane);
        float gc1 = __ldg(gp + 32 + lane);
        float gc2 = __ldg(gp + 64 + lane);

        // ---- A: h = gelu(BN(W_alpha g + b_alpha)) ----
#pragma unroll
        for (int r = 0; r < 4; ++r) {
            int d = d0 + r;
            float hv = sm[WA_ + d] * gc0 + sm[WA_ + 64 + d] * gc1 +
                       sm[WA_ + 128 + d] * gc2 + sm[BA_ + d];
            hv = ((hv - sm[BNM_ + d]) * sm[BNR_ + d]) * sm[BNG_ + d] + sm[BNB_ + d];
            hv = gelu_exact(hv);
            sm[H32_ + d * 33 + lane] = hv;
            sm[HT_ + lane * 68 + d] = hv;
        }
        __syncthreads();

        // ---- B: u = P h ; v = Wv h + bv  (mma, 16 warps) ----
        {
            float cu[4] = {0, 0, 0, 0}, cv[4] = {0, 0, 0, 0};
            int j0 = mt * 16 + qg;
            int n0 = nt * 8 + qg;
#pragma unroll
            for (int kt = 0; kt < 8; ++kt) {
                int c0i = kt * 8 + t4;
                float a0f = sm[HT_ + j0 * 68 + c0i];
                float a1f = sm[HT_ + (j0 + 8) * 68 + c0i];
                float a2f = sm[HT_ + j0 * 68 + c0i + 4];
                float a3f = sm[HT_ + (j0 + 8) * 68 + c0i + 4];
                unsigned ab[4], as_[4];
                split32(a0f, ab[0], as_[0]); split32(a1f, ab[1], as_[1]);
                split32(a2f, ab[2], as_[2]); split32(a3f, ab[3], as_[3]);

                float w0 = sm[PB_ + c0i * 72 + n0];
                float w1 = sm[PB_ + (c0i + 4) * 72 + n0];
                unsigned bb0, bs0, bb1, bs1;
                split32(w0, bb0, bs0); split32(w1, bb1, bs1);
                mma8(cu, ab, bb0, bb1); mma8(cu, ab, bs0, bs1); mma8(cu, as_, bb0, bb1);

                w0 = sm[WVT_ + c0i * 72 + n0];
                w1 = sm[WVT_ + (c0i + 4) * 72 + n0];
                split32(w0, bb0, bs0); split32(w1, bb1, bs1);
                mma8(cv, ab, bb0, bb1); mma8(cv, ab, bs0, bs1); mma8(cv, as_, bb0, bb1);
            }
            int jr0 = mt * 16 + qg, jr1 = jr0 + 8;
            int cc0 = nt * 8 + 2 * t4, cc1 = cc0 + 1;
            sm[U_ + cc0 * 72 + jr0] = cu[0];
            sm[U_ + cc1 * 72 + jr0] = cu[1];
            sm[U_ + cc0 * 72 + jr1] = cu[2];
            sm[U_ + cc1 * 72 + jr1] = cu[3];
            float bv0 = sm[BV_ + cc0], bv1 = sm[BV_ + cc1];
            sm[V_ + jr0 * 72 + cc0] = cv[0] + bv0;
            sm[V_ + jr0 * 72 + cc1] = cv[1] + bv1;
            sm[V_ + jr1 * 72 + cc0] = cv[2] + bv0;
            sm[V_ + jr1 * 72 + cc1] = cv[3] + bv1;
        }
        if (warp == 0) {   // bias dot products (fp32 exact)
            unsigned long long rc = 0;
#pragma unroll 8
            for (int cc = 0; cc < 64; ++cc) {
                float hv = sm[H32_ + cc * 33 + lane];
                rc = fma2_(*(const unsigned long long*)&sm[WQKB_ + 2 * cc],
                           pk2(hv, hv), rc);
            }
            float rB, cA;
            upk2(rc, rB, cA);
            sm[RBs_ + lane] = rB;
            sm[CAs_ + lane] = cA;
        }
        __syncthreads();

        // ---- C: logits = h^T u  (mma, warps 0..7) ----
        if (warp < 8) {
            int cmt = warp >> 2, cnt = warp & 3;
            float cl[4] = {0, 0, 0, 0};
            int i0 = cmt * 16 + qg;
            int n0 = cnt * 8 + qg;
#pragma unroll
            for (int kt = 0; kt < 8; ++kt) {
                int c0i = kt * 8 + t4;
                float a0f = sm[HT_ + i0 * 68 + c0i];
                float a1f = sm[HT_ + (i0 + 8) * 68 + c0i];
                float a2f = sm[HT_ + i0 * 68 + c0i + 4];
                float a3f = sm[HT_ + (i0 + 8) * 68 + c0i + 4];
                unsigned ab[4], as_[4];
                split32(a0f, ab[0], as_[0]); split32(a1f, ab[1], as_[1]);
                split32(a2f, ab[2], as_[2]); split32(a3f, ab[3], as_[3]);
                float w0 = sm[U_ + c0i * 72 + n0];
                float w1 = sm[U_ + (c0i + 4) * 72 + n0];
                unsigned bb0, bs0, bb1, bs1;
                split32(w0, bb0, bs0); split32(w1, bb1, bs1);
                mma8(cl, ab, bb0, bb1); mma8(cl, ab, bs0, bs1); mma8(cl, as_, bb0, bb1);
            }
            int jc0 = cnt * 8 + 2 * t4;
            sm[LG_ + i0 * 33 + jc0]           = cl[0];
            sm[LG_ + i0 * 33 + jc0 + 1]       = cl[1];
            sm[LG_ + (i0 + 8) * 33 + jc0]     = cl[2];
            sm[LG_ + (i0 + 8) * 33 + jc0 + 1] = cl[3];
        }
        __syncthreads();

        // ---- softmax (16 warps, rows warp & warp+16) ----
        {
            float cb = sm[CB_];
            float rB = sm[RBs_ + lane];
            float a0 = (sm[LG_ + warp * 33 + lane] + sm[CAs_ + warp] + rB + cb) * 0.125f;
            float a1 = (sm[LG_ + (warp + 16) * 33 + lane] + sm[CAs_ + warp + 16] + rB + cb) * 0.125f;
            float m0 = a0, m1 = a1;
#pragma unroll
            for (int off = 16; off; off >>= 1) {
                m0 = fmaxf(m0, __shfl_xor_sync(FULLMASK, m0, off));
                m1 = fmaxf(m1, __shfl_xor_sync(FULLMASK, m1, off));
            }
            float e0 = expf(a0 - m0), e1 = expf(a1 - m1);
            float s0 = e0, s1 = e1;
#pragma unroll
            for (int off = 16; off; off >>= 1) {
                s0 += __shfl_xor_sync(FULLMASK, s0, off);
                s1 += __shfl_xor_sync(FULLMASK, s1, off);
            }
            sm[ATT_ + warp * 68 + lane]        = e0 / s0;
            sm[ATT_ + (warp + 16) * 68 + lane] = e1 / s1;
        }
        __syncthreads();

        // ---- D: res = attn v ; T = res + h  (mma, 16 warps) ----
        {
            float cr[4] = {0, 0, 0, 0};
            int i0 = mt * 16 + qg;
            int n0 = nt * 8 + qg;
#pragma unroll
            for (int kt = 0; kt < 4; ++kt) {
                int j0i = kt * 8 + t4;
                float a0f = sm[ATT_ + i0 * 68 + j0i];
                float a1f = sm[ATT_ + (i0 + 8) * 68 + j0i];
                float a2f = sm[ATT_ + i0 * 68 + j0i + 4];
                float a3f = sm[ATT_ + (i0 + 8) * 68 + j0i + 4];
                unsigned ab[4], as_[4];
                split32(a0f, ab[0], as_[0]); split32(a1f, ab[1], as_[1]);
                split32(a2f, ab[2], as_[2]); split32(a3f, ab[3], as_[3]);
                float w0 = sm[V_ + j0i * 72 + n0];
                float w1 = sm[V_ + (j0i + 4) * 72 + n0];
                unsigned bb0, bs0, bb1, bs1;
                split32(w0, bb0, bs0); split32(w1, bb1, bs1);
                mma8(cr, ab, bb0, bb1); mma8(cr, ab, bs0, bs1); mma8(cr, as_, bb0, bb1);
            }
            int dc0 = nt * 8 + 2 * t4, dc1 = dc0 + 1;
            int i1 = i0 + 8;
            sm[RES_ + i0 * 68 + dc0] = cr[0];
            sm[RES_ + i0 * 68 + dc1] = cr[1];
            sm[RES_ + i1 * 68 + dc0] = cr[2];
            sm[RES_ + i1 * 68 + dc1] = cr[3];
            sm[T32_ + i0 * 68 + dc0] = cr[0] + sm[HT_ + i0 * 68 + dc0];
            sm[T32_ + i0 * 68 + dc1] = cr[1] + sm[HT_ + i0 * 68 + dc1];
            sm[T32_ + i1 * 68 + dc0] = cr[2] + sm[HT_ + i1 * 68 + dc0];
            sm[T32_ + i1 * 68 + dc1] = cr[3] + sm[HT_ + i1 * 68 + dc1];
        }
        __syncthreads();

        // ---- E: G1 = gelu(Wg1 T + bg1)  (mma, 16 warps) ----
        {
            float cg[4] = {0, 0, 0, 0};
            int i0 = mt * 16 + qg;
            int n0 = nt * 8 + qg;
#pragma unroll
            for (int kt = 0; kt < 8; ++kt) {
                int c0i = kt * 8 + t4;
                float a0f = sm[T32_ + i0 * 68 + c0i];
                float a1f = sm[T32_ + (i0 + 8) * 68 + c0i];
                float a2f = sm[T32_ + i0 * 68 + c0i + 4];
                float a3f = sm[T32_ + (i0 + 8) * 68 + c0i + 4];
                unsigned ab[4], as_[4];
                split32(a0f, ab[0], as_[0]); split32(a1f, ab[1], as_[1]);
                split32(a2f, ab[2], as_[2]); split32(a3f, ab[3], as_[3]);
                float w0 = sm[WG1T_ + c0i * 72 + n0];
                float w1 = sm[WG1T_ + (c0i + 4) * 72 + n0];
                unsigned bb0, bs0, bb1, bs1;
                split32(w0, bb0, bs0); split32(w1, bb1, bs1);
                mma8(cg, ab, bb0, bb1); mma8(cg, ab, bs0, bs1); mma8(cg, as_, bb0, bb1);
            }
            int dc0 = nt * 8 + 2 * t4, dc1 = dc0 + 1;
            int i1 = i0 + 8;
            float g10 = sm[BG1_ + dc0], g11 = sm[BG1_ + dc1];
            sm[G132_ + i0 * 68 + dc0] = gelu_exact(cg[0] + g10);
            sm[G132_ + i0 * 68 + dc1] = gelu_exact(cg[1] + g11);
            sm[G132_ + i1 * 68 + dc0] = gelu_exact(cg[2] + g10);
            sm[G132_ + i1 * 68 + dc1] = gelu_exact(cg[3] + g11);
        }
        __syncthreads();

        // ---- F: out = Wg2 G1 + bg2 + res ; maxpool over group dim ----
        {
            float cf[4] = {0, 0, 0, 0};
            int i0 = mt * 16 + qg;
            int n0 = nt * 8 + qg;
#pragma unroll
            for (int kt = 0; kt < 8; ++kt) {
                int c0i = kt * 8 + t4;
                float a0f = sm[G132_ + i0 * 68 + c0i];
                float a1f = sm[G132_ + (i0 + 8) * 68 + c0i];
                float a2f = sm[G132_ + i0 * 68 + c0i + 4];
                float a3f = sm[G132_ + (i0 + 8) * 68 + c0i + 4];
                unsigned ab[4], as_[4];
                split32(a0f, ab[0], as_[0]); split32(a1f, ab[1], as_[1]);
                split32(a2f, ab[2], as_[2]); split32(a3f, ab[3], as_[3]);
                float w0 = sm[WG2T_ + c0i * 72 + n0];
                float w1 = sm[WG2T_ + (c0i + 4) * 72 + n0];
                unsigned bb0, bs0, bb1, bs1;
                split32(w0, bb0, bs0); split32(w1, bb1, bs1);
                mma8(cf, ab, bb0, bb1); mma8(cf, ab, bs0, bs1); mma8(cf, as_, bb0, bb1);
            }
            int dc0 = nt * 8 + 2 * t4, dc1 = dc0 + 1;
            int i1 = i0 + 8;
            float v0 = cf[0] + sm[BG2_ + dc0] + sm[RES_ + i0 * 68 + dc0];
            float v1 = cf[1] + sm[BG2_ + dc1] + sm[RES_ + i0 * 68 + dc1];
            float v2 = cf[2] + sm[BG2_ + dc0] + sm[RES_ + i1 * 68 + dc0];
            float v3 = cf[3] + sm[BG2_ + dc1] + sm[RES_ + i1 * 68 + dc1];
            float m0 = fmaxf(v0, v2), m1 = fmaxf(v1, v3);
#pragma unroll
            for (int off = 4; off < 32; off <<= 1) {
                m0 = fmaxf(m0, __shfl_xor_sync(FULLMASK, m0, off));
                m1 = fmaxf(m1, __shfl_xor_sync(FULLMASK, m1, off));
            }
            if (lane < 4) {
                sm[MP_ + mt * 64 + nt * 8 + 2 * t4]     = m0;
                sm[MP_ + mt * 64 + nt * 8 + 2 * t4 + 1] = m1;
            }
        }
        __syncthreads();
        if (tid < 64)
            out[(size_t)g * 67 + 3 + tid] =
                fmaxf(sm[MP_ + tid], sm[MP_ + 64 + tid]);
        __syncthreads();
    }
}

// ============================ launch ======================================
extern "C" void kernel_launch(void* const* d_in, const int* in_sizes, int n_in,
                              void* d_out, int out_size) {
    (void)in_sizes; (void)n_in; (void)out_size;
    const float* x        = (const float*)d_in[0];
    const float* w_alpha  = (const float*)d_in[1];
    const float* b_alpha  = (const float*)d_in[2];
    const float* bn_gamma = (const float*)d_in[3];
    const float* bn_beta  = (const float*)d_in[4];
    const float* bn_mean  = (const float*)d_in[5];
    const float* bn_var   = (const float*)d_in[6];
    const float* w_q      = (const float*)d_in[7];
    const float* b_q      = (const float*)d_in[8];
    const float* w_k      = (const float*)d_in[9];
    const float* b_k      = (const float*)d_in[10];
    const float* w_v      = (const float*)d_in[11];
    const float* b_v      = (const float*)d_in[12];
    const float* w_g1     = (const float*)d_in[13];
    const float* b_g1     = (const float*)d_in[14];
    const float* w_g2     = (const float*)d_in[15];
    const float* b_g2     = (const float*)d_in[16];
    float* out = (float*)d_out;

    cudaFuncSetAttribute(fps_kernel,
                         cudaFuncAttributeMaxDynamicSharedMemorySize, 49664);
    cudaFuncSetAttribute(knn_kernel,
                         cudaFuncAttributeMaxDynamicSharedMemorySize, 65536);
    cudaFuncSetAttribute(group_kernel,
                         cudaFuncAttributeMaxDynamicSharedMemorySize, SMTOT * 4);

    fps_kernel<<<B_, 512, 49664>>>(x, out);
    knn_kernel<<<B_ * 4, 512, 65536>>>(x);
    group_kernel<<<148, 512, SMTOT * 4>>>(w_alpha, b_alpha, bn_gamma, bn_beta,
                                          bn_mean, bn_var, w_q, b_q, w_k, b_k,
                                          w_v, b_v, w_g1, b_g1, w_g2, b_g2, out);
}

// round 6
// speedup vs baseline: 1.8204x; 1.3186x over previous
#include <cuda_runtime.h>
#include <math.h>

#define B_   32
#define N_   4096
#define S_   512
#define FULLMASK 0xffffffffu

__device__ float g_centroid[B_ * S_ * 3];
__device__ float g_groups[B_ * S_ * 96];   // [bs][c][k]

// ---------------- helpers -------------------------------------------------
__device__ __forceinline__ unsigned long long pk2(float lo, float hi) {
    unsigned long long r;
    asm("mov.b64 %0, {%1, %2};" : "=l"(r) : "f"(lo), "f"(hi));
    return r;
}
__device__ __forceinline__ void upk2(unsigned long long v, float& lo, float& hi) {
    asm("mov.b64 {%0, %1}, %2;" : "=f"(lo), "=f"(hi) : "l"(v));
}
__device__ __forceinline__ unsigned long long fma2_(unsigned long long a,
                                                   unsigned long long b,
                                                   unsigned long long c) {
    unsigned long long d;
    asm("fma.rn.f32x2 %0, %1, %2, %3;" : "=l"(d) : "l"(a), "l"(b), "l"(c));
    return d;
}
__device__ __forceinline__ unsigned short bh16(float x) {
    unsigned short r;
    asm("cvt.rn.bf16.f32 %0, %1;" : "=h"(r) : "f"(x));
    return r;
}
__device__ __forceinline__ float bf2f(unsigned short h) {
    return __uint_as_float((unsigned)h << 16);
}
__device__ __forceinline__ void bsplit(float x, unsigned short& h, unsigned short& l) {
    h = bh16(x);
    l = bh16(x - bf2f(h));
}
__device__ __forceinline__ unsigned pk16(unsigned short a, unsigned short b) {
    return (unsigned)a | ((unsigned)b << 16);
}
// split x and pack both bf16 words into one u32 (h lo, l hi) for shfl pairing
__device__ __forceinline__ unsigned bsplitw(float x) {
    unsigned short h, l;
    bsplit(x, h, l);
    return pk16(h, l);
}
__device__ __forceinline__ void mma16(float* c, const unsigned* a,
                                      unsigned b0, unsigned b1) {
    asm("mma.sync.aligned.m16n8k16.row.col.f32.bf16.bf16.f32 "
        "{%0,%1,%2,%3},{%4,%5,%6,%7},{%8,%9},{%0,%1,%2,%3};"
        : "+f"(c[0]), "+f"(c[1]), "+f"(c[2]), "+f"(c[3])
        : "r"(a[0]), "r"(a[1]), "r"(a[2]), "r"(a[3]), "r"(b0), "r"(b1));
}
__device__ __forceinline__ float gelu_exact(float v) {
    return 0.5f * v * (1.0f + erff(v * 0.70710678118654752440f));
}

// ============================ FPS =========================================
__global__ __launch_bounds__(512) void fps_kernel(const float* __restrict__ x,
                                                  float* __restrict__ out) {
    extern __shared__ float smf[];
    float* sx0 = smf;
    float* sx1 = smf + 4096;
    float* sx2 = smf + 8192;
    unsigned long long* pb = (unsigned long long*)(smf + 12288);

    int b = blockIdx.x, tid = threadIdx.x;
    int lane = tid & 31, warp = tid >> 5;
    const float* xb = x + (size_t)b * N_ * 3;

    float px[8], py[8], pz[8], dist[8];
#pragma unroll
    for (int i = 0; i < 8; ++i) {
        int n = tid + i * 512;
        float a0 = xb[n * 3 + 0], a1 = xb[n * 3 + 1], a2 = xb[n * 3 + 2];
        px[i] = a0; py[i] = a1; pz[i] = a2;
        sx0[n] = a0; sx1[n] = a1; sx2[n] = a2;
        dist[i] = 1e10f;
    }
    __syncthreads();

    int last = 0;
    for (int s = 0; s < S_; ++s) {
        float c0 = sx0[last], c1 = sx1[last], c2 = sx2[last];
        if (tid == 0) {
            int bs = b * S_ + s;
            out[(size_t)bs * 67 + 0] = c0;
            out[(size_t)bs * 67 + 1] = c1;
            out[(size_t)bs * 67 + 2] = c2;
            g_centroid[bs * 3 + 0] = c0;
            g_centroid[bs * 3 + 1] = c1;
            g_centroid[bs * 3 + 2] = c2;
        }
        float bv = -1.0f;
        unsigned bi = 0;
#pragma unroll
        for (int i = 0; i < 8; ++i) {
            float dx = px[i] - c0, dy = py[i] - c1, dz = pz[i] - c2;
            float d = (dx * dx + dy * dy) + dz * dz;
            float nd = fminf(dist[i], d);
            dist[i] = nd;
            if (nd > bv) { bv = nd; bi = (unsigned)(tid + i * 512); }
        }
        unsigned vb = __float_as_uint(bv);
        unsigned wmax = __reduce_max_sync(FULLMASK, vb);
        unsigned cand = (vb == wmax) ? bi : 0xffffffffu;
        unsigned widx = __reduce_min_sync(FULLMASK, cand);
        int par = s & 1;
        if (lane == 0)
            pb[par * 16 + warp] =
                ((unsigned long long)wmax << 32) |
                (unsigned long long)(0xffffffffu - widx);
        __syncthreads();
        unsigned long long best = 0;
#pragma unroll
        for (int w = 0; w < 16; ++w) {
            unsigned long long k = pb[par * 16 + w];
            best = (k > best) ? k : best;
        }
        last = (int)(0xffffffffu - (unsigned)best);
    }
}

// ============================ KNN (2 centroids / warp) ====================
__global__ __launch_bounds__(512) void knn_kernel(const float* __restrict__ x) {
    int b    = blockIdx.x >> 2;
    int part = blockIdx.x & 3;
    extern __shared__ float smk[];
    float* sx0 = smk;
    float* sx1 = smk + 4096;
    float* sx2 = smk + 8192;
    float* sxs = smk + 12288;

    const float* xb = x + (size_t)b * N_ * 3;
    for (int i = threadIdx.x; i < N_; i += 512) {
        float a0 = xb[i * 3 + 0], a1 = xb[i * 3 + 1], a2 = xb[i * 3 + 2];
        sx0[i] = a0; sx1[i] = a1; sx2[i] = a2;
        sxs[i] = (a0 * a0 + a1 * a1) + a2 * a2;
    }
    __syncthreads();

    int warp = threadIdx.x >> 5, lane = threadIdx.x & 31;
    for (int jj = 0; jj < 4; ++jj) {
        int sA = part * 128 + jj * 32 + warp * 2;
        int bsA = b * S_ + sA, bsB = bsA + 1;
        float cA0 = g_centroid[bsA * 3 + 0], cA1 = g_centroid[bsA * 3 + 1],
              cA2 = g_centroid[bsA * 3 + 2];
        float cB0 = g_centroid[bsB * 3 + 0], cB1 = g_centroid[bsB * 3 + 1],
              cB2 = g_centroid[bsB * 3 + 2];
        float csA = (cA0 * cA0 + cA1 * cA1) + cA2 * cA2;
        float csB = (cB0 * cB0 + cB1 * cB1) + cB2 * cB2;

        float lvA = 3.402823466e38f, lvB = 3.402823466e38f;
        int   liA = -1, liB = -1;
        for (int base = 0; base < N_; base += 32) {
            int n = base + lane;
            float p0 = sx0[n], p1 = sx1[n], p2 = sx2[n], ps = sxs[n];
            float d2A = (csA + ps) - 2.0f * ((cA0 * p0 + cA1 * p1) + cA2 * p2);
            float d2B = (csB + ps) - 2.0f * ((cB0 * p0 + cB1 * p1) + cB2 * p2);

            float thr = __shfl_sync(FULLMASK, lvA, 31);
            unsigned m = __ballot_sync(FULLMASK, d2A < thr);
            while (m) {
                int src = __ffs(m) - 1;
                m &= m - 1;
                float cd = __shfl_sync(FULLMASK, d2A, src);
                int   cn = base + src;
                thr = __shfl_sync(FULLMASK, lvA, 31);
                if (cd < thr) {
                    unsigned keep = __ballot_sync(FULLMASK,
                        (lvA < cd) || (lvA == cd && liA < cn));
                    int pos = __popc(keep);
                    float pv = __shfl_up_sync(FULLMASK, lvA, 1);
                    int   pi = __shfl_up_sync(FULLMASK, liA, 1);
                    if (lane == pos)      { lvA = cd; liA = cn; }
                    else if (lane > pos)  { lvA = pv; liA = pi; }
                }
            }
            thr = __shfl_sync(FULLMASK, lvB, 31);
            m = __ballot_sync(FULLMASK, d2B < thr);
            while (m) {
                int src = __ffs(m) - 1;
                m &= m - 1;
                float cd = __shfl_sync(FULLMASK, d2B, src);
                int   cn = base + src;
                thr = __shfl_sync(FULLMASK, lvB, 31);
                if (cd < thr) {
                    unsigned keep = __ballot_sync(FULLMASK,
                        (lvB < cd) || (lvB == cd && liB < cn));
                    int pos = __popc(keep);
                    float pv = __shfl_up_sync(FULLMASK, lvB, 1);
                    int   pi = __shfl_up_sync(FULLMASK, liB, 1);
                    if (lane == pos)      { lvB = cd; liB = cn; }
                    else if (lane > pos)  { lvB = pv; liB = pi; }
                }
            }
        }
        float* gpA = g_groups + (size_t)bsA * 96;
        gpA[lane]      = sx0[liA] - cA0;
        gpA[32 + lane] = sx1[liA] - cA1;
        gpA[64 + lane] = sx2[liA] - cA2;
        float* gpB = g_groups + (size_t)bsB * 96;
        gpB[lane]      = sx0[liB] - cB0;
        gpB[32 + lane] = sx1[liB] - cB1;
        gpB[64 + lane] = sx2[liB] - cB2;
    }
}

// ======================= per-group compute (3xBF16 mma) ===================
// word offsets in dynamic smem
#define PBh_   0        // [kp_cc=32][c] stride 72  (u32)
#define PBl_   2304
#define WVh_   4608     // [kp_c=32][d] stride 72
#define WVl_   6912
#define WG1h_  9216
#define WG1l_  11520
#define WG2h_  13824
#define WG2l_  16128
#define WA_    18432
#define WQKB_  18624
#define BV_    18752
#define BG1_   18816
#define BG2_   18880
#define BA_    18944
#define BNM_   19008
#define BNR_   19072
#define BNG_   19136
#define BNB_   19200
#define CB_    19264
#define H32_   19272    // f32 [d=64][j] stride 33
#define Hh_    21384    // u32 [j=32][kp=32] stride 36
#define Hl_    22536
#define Uh_    23688    // u32 [kp_c=32][j] stride 40
#define Ul_    24968
#define Vh_    26248    // u32 [kp_j=16][d] stride 72
#define Vl_    27400
#define ATTh_  28552    // u32 [i=32][kp=16] stride 20
#define ATTl_  29192
#define Th_    29832    // u32 [i=32][kp=32] stride 36
#define Tl_    30984
#define G1h_   32136
#define G1l_   33288
#define LG_    34440    // f32 [i=32][j] stride 33
#define RBs_   35496
#define CAs_   35528
#define MP_    35560
#define SMTOT  35688    // words -> 142752 bytes
// init scratch (overlaps H32.. region, used before main loop only)
#define SCRQ_  19272
#define SCRK_  23368
#define SCRP_  27464

__global__ __launch_bounds__(512) void group_kernel(
    const float* __restrict__ w_alpha, const float* __restrict__ b_alpha,
    const float* __restrict__ bn_gamma, const float* __restrict__ bn_beta,
    const float* __restrict__ bn_mean,  const float* __restrict__ bn_var,
    const float* __restrict__ w_q, const float* __restrict__ b_q,
    const float* __restrict__ w_k, const float* __restrict__ b_k,
    const float* __restrict__ w_v, const float* __restrict__ b_v,
    const float* __restrict__ w_g1, const float* __restrict__ b_g1,
    const float* __restrict__ w_g2, const float* __restrict__ b_g2,
    float* __restrict__ out) {
    extern __shared__ float sm[];
    unsigned* su = (unsigned*)sm;
    int tid = threadIdx.x;
    int warp = tid >> 5, lane = tid & 31;
    int qg = lane >> 2, t4 = lane & 3;

    // ---- init phase 1: raw wq/wk; convert Wv/Wg1/Wg2 to split-bf16 ----
    for (int i = tid; i < 4096; i += 512) {
        sm[SCRQ_ + i] = w_q[i];
        sm[SCRK_ + i] = w_k[i];
    }
    for (int i = tid; i < 2048; i += 512) {
        int d = i >> 5, cp = i & 31;
        int i0 = d * 64 + 2 * cp;
        unsigned short h0, l0, h1, l1;
        bsplit(w_v[i0], h0, l0); bsplit(w_v[i0 + 1], h1, l1);
        su[WVh_ + cp * 72 + d] = pk16(h0, h1);
        su[WVl_ + cp * 72 + d] = pk16(l0, l1);
        bsplit(w_g1[i0], h0, l0); bsplit(w_g1[i0 + 1], h1, l1);
        su[WG1h_ + cp * 72 + d] = pk16(h0, h1);
        su[WG1l_ + cp * 72 + d] = pk16(l0, l1);
        bsplit(w_g2[i0], h0, l0); bsplit(w_g2[i0 + 1], h1, l1);
        su[WG2h_ + cp * 72 + d] = pk16(h0, h1);
        su[WG2l_ + cp * 72 + d] = pk16(l0, l1);
    }
    if (tid < 192) { int d = tid / 3, c = tid % 3; sm[WA_ + c * 64 + d] = w_alpha[tid]; }
    if (tid < 64) {
        sm[BV_ + tid] = b_v[tid];
        sm[BG1_ + tid] = b_g1[tid]; sm[BG2_ + tid] = b_g2[tid];
        sm[BA_ + tid] = b_alpha[tid];
        sm[BNM_ + tid] = bn_mean[tid];
        sm[BNR_ + tid] = rsqrtf(bn_var[tid] + 1e-5f);
        sm[BNG_ + tid] = bn_gamma[tid];
        sm[BNB_ + tid] = bn_beta[tid];
    }
    __syncthreads();

    // ---- init phase 2: P = Wq^T Wk (f32), folded bias vectors ----
    for (int i = tid; i < 4096; i += 512) {
        int c = i & 63, cc = i >> 6;
        float s = 0.f;
#pragma unroll 8
        for (int d = 0; d < 64; ++d)
            s += sm[SCRQ_ + d * 64 + c] * sm[SCRK_ + d * 64 + cc];
        sm[SCRP_ + cc * 64 + c] = s;
    }
    if (tid < 64) {
        int c = tid;
        float aq = 0.f, ak = 0.f;
#pragma unroll 8
        for (int d = 0; d < 64; ++d) {
            aq += sm[SCRQ_ + d * 64 + c] * b_k[d];   // Wq^T b_k
            ak += sm[SCRK_ + d * 64 + c] * b_q[d];   // Wk^T b_q
        }
        sm[WQKB_ + 2 * c]     = ak;
        sm[WQKB_ + 2 * c + 1] = aq;
    }
    if (tid == 511) {
        float s = 0.f;
        for (int d = 0; d < 64; ++d) s += b_q[d] * b_k[d];
        sm[CB_] = s;
    }
    __syncthreads();

    // ---- init phase 3: convert P to split-bf16 ----
    for (int i = tid; i < 2048; i += 512) {
        int ccp = i >> 6, c = i & 63;
        unsigned short h0, l0, h1, l1;
        bsplit(sm[SCRP_ + (2 * ccp) * 64 + c], h0, l0);
        bsplit(sm[SCRP_ + (2 * ccp + 1) * 64 + c], h1, l1);
        su[PBh_ + ccp * 72 + c] = pk16(h0, h1);
        su[PBl_ + ccp * 72 + c] = pk16(l0, l1);
    }
    __syncthreads();

    int mt = warp >> 3, nt = warp & 7;
    int d0 = warp * 4;

    for (int g = blockIdx.x; g < B_ * S_; g += gridDim.x) {
        const float* gp = g_groups + (size_t)g * 96;
        float gc0 = __ldg(gp + lane);
        float gc1 = __ldg(gp + 32 + lane);
        float gc2 = __ldg(gp + 64 + lane);

        // ---- A: h = gelu(BN(W_alpha g + b_alpha)) ----
        {
            float hv[4];
#pragma unroll
            for (int r = 0; r < 4; ++r) {
                int d = d0 + r;
                float v = sm[WA_ + d] * gc0 + sm[WA_ + 64 + d] * gc1 +
                          sm[WA_ + 128 + d] * gc2 + sm[BA_ + d];
                v = ((v - sm[BNM_ + d]) * sm[BNR_ + d]) * sm[BNG_ + d] + sm[BNB_ + d];
                v = gelu_exact(v);
                hv[r] = v;
                sm[H32_ + d * 33 + lane] = v;
            }
            unsigned short h0, l0, h1, l1;
            bsplit(hv[0], h0, l0); bsplit(hv[1], h1, l1);
            su[Hh_ + lane * 36 + 2 * warp]     = pk16(h0, h1);
            su[Hl_ + lane * 36 + 2 * warp]     = pk16(l0, l1);
            bsplit(hv[2], h0, l0); bsplit(hv[3], h1, l1);
            su[Hh_ + lane * 36 + 2 * warp + 1] = pk16(h0, h1);
            su[Hl_ + lane * 36 + 2 * warp + 1] = pk16(l0, l1);
        }
        __syncthreads();

        // ---- B: u = P h ; v = Wv h + bv  (all 16 warps) ----
        {
            int ra0 = mt * 16 + qg, ra1 = ra0 + 8;
            int n0 = nt * 8 + qg;
            float uh[4] = {0, 0, 0, 0}, ue[4] = {0, 0, 0, 0};
            float vh[4] = {0, 0, 0, 0}, ve[4] = {0, 0, 0, 0};
#pragma unroll
            for (int kt = 0; kt < 4; ++kt) {
                int kp0 = kt * 8 + t4, kp1 = kp0 + 4;
                unsigned ah[4], al[4];
                ah[0] = su[Hh_ + ra0 * 36 + kp0];
                ah[1] = su[Hh_ + ra1 * 36 + kp0];
                ah[2] = su[Hh_ + ra0 * 36 + kp1];
                ah[3] = su[Hh_ + ra1 * 36 + kp1];
                al[0] = su[Hl_ + ra0 * 36 + kp0];
                al[1] = su[Hl_ + ra1 * 36 + kp0];
                al[2] = su[Hl_ + ra0 * 36 + kp1];
                al[3] = su[Hl_ + ra1 * 36 + kp1];
                unsigned bh0 = su[PBh_ + kp0 * 72 + n0];
                unsigned bh1 = su[PBh_ + kp1 * 72 + n0];
                unsigned bl0 = su[PBl_ + kp0 * 72 + n0];
                unsigned bl1 = su[PBl_ + kp1 * 72 + n0];
                mma16(uh, ah, bh0, bh1);
                mma16(ue, ah, bl0, bl1);
                mma16(ue, al, bh0, bh1);
                bh0 = su[WVh_ + kp0 * 72 + n0];
                bh1 = su[WVh_ + kp1 * 72 + n0];
                bl0 = su[WVl_ + kp0 * 72 + n0];
                bl1 = su[WVl_ + kp1 * 72 + n0];
                mma16(vh, ah, bh0, bh1);
                mma16(ve, ah, bl0, bl1);
                mma16(ve, al, bh0, bh1);
            }
            int cc0 = nt * 8 + 2 * t4, cc1 = cc0 + 1;
            int jr0 = mt * 16 + qg, jr1 = jr0 + 8;
            float u0 = uh[0] + ue[0], u1 = uh[1] + ue[1];
            float u2 = uh[2] + ue[2], u3 = uh[3] + ue[3];
            float bv0 = sm[BV_ + cc0], bv1 = sm[BV_ + cc1];
            float v0 = vh[0] + ve[0] + bv0, v1 = vh[1] + ve[1] + bv1;
            float v2 = vh[2] + ve[2] + bv0, v3 = vh[3] + ve[3] + bv1;
            // U pack (c-pairs local)
            int kpU = nt * 4 + t4;
            unsigned short h0, l0, h1, l1;
            bsplit(u0, h0, l0); bsplit(u1, h1, l1);
            su[Uh_ + kpU * 40 + jr0] = pk16(h0, h1);
            su[Ul_ + kpU * 40 + jr0] = pk16(l0, l1);
            bsplit(u2, h0, l0); bsplit(u3, h1, l1);
            su[Uh_ + kpU * 40 + jr1] = pk16(h0, h1);
            su[Ul_ + kpU * 40 + jr1] = pk16(l0, l1);
            // V pack (j-pairs via shfl_xor 4)
            unsigned s0 = bsplitw(v0), s1 = bsplitw(v1);
            unsigned s2 = bsplitw(v2), s3 = bsplitw(v3);
            unsigned p0 = __shfl_xor_sync(FULLMASK, s0, 4);
            unsigned p1 = __shfl_xor_sync(FULLMASK, s1, 4);
            unsigned p2 = __shfl_xor_sync(FULLMASK, s2, 4);
            unsigned p3 = __shfl_xor_sync(FULLMASK, s3, 4);
            if ((qg & 1) == 0) {
                int kv0 = mt * 8 + (qg >> 1);
                int kv1 = kv0 + 4;
                su[Vh_ + kv0 * 72 + cc0] = __byte_perm(s0, p0, 0x5410);
                su[Vl_ + kv0 * 72 + cc0] = __byte_perm(s0, p0, 0x7632);
                su[Vh_ + kv0 * 72 + cc1] = __byte_perm(s1, p1, 0x5410);
                su[Vl_ + kv0 * 72 + cc1] = __byte_perm(s1, p1, 0x7632);
                su[Vh_ + kv1 * 72 + cc0] = __byte_perm(s2, p2, 0x5410);
                su[Vl_ + kv1 * 72 + cc0] = __byte_perm(s2, p2, 0x7632);
                su[Vh_ + kv1 * 72 + cc1] = __byte_perm(s3, p3, 0x5410);
                su[Vl_ + kv1 * 72 + cc1] = __byte_perm(s3, p3, 0x7632);
            }
        }
        if (warp == 0) {   // bias dot products (fp32 exact)
            unsigned long long rc = 0;
#pragma unroll 8
            for (int cc = 0; cc < 64; ++cc) {
                float hv = sm[H32_ + cc * 33 + lane];
                rc = fma2_(*(const unsigned long long*)&sm[WQKB_ + 2 * cc],
                           pk2(hv, hv), rc);
            }
            float rB, cA;
            upk2(rc, rB, cA);
            sm[RBs_ + lane] = rB;
            sm[CAs_ + lane] = cA;
        }
        __syncthreads();

        // ---- C: logits = h^T u  (warps 0..7) ----
        if (warp < 8) {
            int cmt = warp >> 2, cnt = warp & 3;
            int ra0 = cmt * 16 + qg, ra1 = ra0 + 8;
            int n0 = cnt * 8 + qg;
            float ch[4] = {0, 0, 0, 0}, ce[4] = {0, 0, 0, 0};
#pragma unroll
            for (int kt = 0; kt < 4; ++kt) {
                int kp0 = kt * 8 + t4, kp1 = kp0 + 4;
                unsigned ah[4], al[4];
                ah[0] = su[Hh_ + ra0 * 36 + kp0];
                ah[1] = su[Hh_ + ra1 * 36 + kp0];
                ah[2] = su[Hh_ + ra0 * 36 + kp1];
                ah[3] = su[Hh_ + ra1 * 36 + kp1];
                al[0] = su[Hl_ + ra0 * 36 + kp0];
                al[1] = su[Hl_ + ra1 * 36 + kp0];
                al[2] = su[Hl_ + ra0 * 36 + kp1];
                al[3] = su[Hl_ + ra1 * 36 + kp1];
                unsigned bh0 = su[Uh_ + kp0 * 40 + n0];
                unsigned bh1 = su[Uh_ + kp1 * 40 + n0];
                unsigned bl0 = su[Ul_ + kp0 * 40 + n0];
                unsigned bl1 = su[Ul_ + kp1 * 40 + n0];
                mma16(ch, ah, bh0, bh1);
                mma16(ce, ah, bl0, bl1);
                mma16(ce, al, bh0, bh1);
            }
            int jc0 = cnt * 8 + 2 * t4;
            sm[LG_ + ra0 * 33 + jc0]     = ch[0] + ce[0];
            sm[LG_ + ra0 * 33 + jc0 + 1] = ch[1] + ce[1];
            sm[LG_ + ra1 * 33 + jc0]     = ch[2] + ce[2];
            sm[LG_ + ra1 * 33 + jc0 + 1] = ch[3] + ce[3];
        }
        __syncthreads();

        // ---- softmax (16 warps, rows warp & warp+16) + ATT pack ----
        {
            float cb = sm[CB_];
            float rB = sm[RBs_ + lane];
            float a0 = (sm[LG_ + warp * 33 + lane] + sm[CAs_ + warp] + rB + cb) * 0.125f;
            float a1 = (sm[LG_ + (warp + 16) * 33 + lane] + sm[CAs_ + warp + 16] + rB + cb) * 0.125f;
            float m0 = a0, m1 = a1;
#pragma unroll
            for (int off = 16; off; off >>= 1) {
                m0 = fmaxf(m0, __shfl_xor_sync(FULLMASK, m0, off));
                m1 = fmaxf(m1, __shfl_xor_sync(FULLMASK, m1, off));
            }
            float e0 = expf(a0 - m0), e1 = expf(a1 - m1);
            float s0 = e0, s1 = e1;
#pragma unroll
            for (int off = 16; off; off >>= 1) {
                s0 += __shfl_xor_sync(FULLMASK, s0, off);
                s1 += __shfl_xor_sync(FULLMASK, s1, off);
            }
            float p0f = e0 / s0, p1f = e1 / s1;
            unsigned w0 = bsplitw(p0f), w1 = bsplitw(p1f);
            unsigned q0 = __shfl_xor_sync(FULLMASK, w0, 1);
            unsigned q1 = __shfl_xor_sync(FULLMASK, w1, 1);
            if ((lane & 1) == 0) {
                int jp = lane >> 1;
                su[ATTh_ + warp * 20 + jp]        = __byte_perm(w0, q0, 0x5410);
                su[ATTl_ + warp * 20 + jp]        = __byte_perm(w0, q0, 0x7632);
                su[ATTh_ + (warp + 16) * 20 + jp] = __byte_perm(w1, q1, 0x5410);
                su[ATTl_ + (warp + 16) * 20 + jp] = __byte_perm(w1, q1, 0x7632);
            }
        }
        __syncthreads();

        // ---- D: res = attn v ; T = res + h (res kept in regs) ----
        float r0, r1, r2, r3;
        {
            int ra0 = mt * 16 + qg, ra1 = ra0 + 8;
            int n0 = nt * 8 + qg;
            float rh[4] = {0, 0, 0, 0}, re[4] = {0, 0, 0, 0};
#pragma unroll
            for (int kt = 0; kt < 2; ++kt) {
                int kp0 = kt * 8 + t4, kp1 = kp0 + 4;
                unsigned ah[4], al[4];
                ah[0] = su[ATTh_ + ra0 * 20 + kp0];
                ah[1] = su[ATTh_ + ra1 * 20 + kp0];
                ah[2] = su[ATTh_ + ra0 * 20 + kp1];
                ah[3] = su[ATTh_ + ra1 * 20 + kp1];
                al[0] = su[ATTl_ + ra0 * 20 + kp0];
                al[1] = su[ATTl_ + ra1 * 20 + kp0];
                al[2] = su[ATTl_ + ra0 * 20 + kp1];
                al[3] = su[ATTl_ + ra1 * 20 + kp1];
                unsigned bh0 = su[Vh_ + kp0 * 72 + n0];
                unsigned bh1 = su[Vh_ + kp1 * 72 + n0];
                unsigned bl0 = su[Vl_ + kp0 * 72 + n0];
                unsigned bl1 = su[Vl_ + kp1 * 72 + n0];
                mma16(rh, ah, bh0, bh1);
                mma16(re, ah, bl0, bl1);
                mma16(re, al, bh0, bh1);
            }
            r0 = rh[0] + re[0]; r1 = rh[1] + re[1];
            r2 = rh[2] + re[2]; r3 = rh[3] + re[3];
            int dc0 = nt * 8 + 2 * t4, dc1 = dc0 + 1;
            float t0 = r0 + sm[H32_ + dc0 * 33 + ra0];
            float t1 = r1 + sm[H32_ + dc1 * 33 + ra0];
            float t2 = r2 + sm[H32_ + dc0 * 33 + ra1];
            float t3 = r3 + sm[H32_ + dc1 * 33 + ra1];
            int kpT = nt * 4 + t4;
            unsigned short h0, l0, h1, l1;
            bsplit(t0, h0, l0); bsplit(t1, h1, l1);
            su[Th_ + ra0 * 36 + kpT] = pk16(h0, h1);
            su[Tl_ + ra0 * 36 + kpT] = pk16(l0, l1);
            bsplit(t2, h0, l0); bsplit(t3, h1, l1);
            su[Th_ + ra1 * 36 + kpT] = pk16(h0, h1);
            su[Tl_ + ra1 * 36 + kpT] = pk16(l0, l1);
        }
        __syncthreads();

        // ---- E: G1 = gelu(Wg1 T + bg1) ----
        {
            int ra0 = mt * 16 + qg, ra1 = ra0 + 8;
            int n0 = nt * 8 + qg;
            float gh[4] = {0, 0, 0, 0}, ge[4] = {0, 0, 0, 0};
#pragma unroll
            for (int kt = 0; kt < 4; ++kt) {
                int kp0 = kt * 8 + t4, kp1 = kp0 + 4;
                unsigned ah[4], al[4];
                ah[0] = su[Th_ + ra0 * 36 + kp0];
                ah[1] = su[Th_ + ra1 * 36 + kp0];
                ah[2] = su[Th_ + ra0 * 36 + kp1];
                ah[3] = su[Th_ + ra1 * 36 + kp1];
                al[0] = su[Tl_ + ra0 * 36 + kp0];
                al[1] = su[Tl_ + ra1 * 36 + kp0];
                al[2] = su[Tl_ + ra0 * 36 + kp1];
                al[3] = su[Tl_ + ra1 * 36 + kp1];
                unsigned bh0 = su[WG1h_ + kp0 * 72 + n0];
                unsigned bh1 = su[WG1h_ + kp1 * 72 + n0];
                unsigned bl0 = su[WG1l_ + kp0 * 72 + n0];
                unsigned bl1 = su[WG1l_ + kp1 * 72 + n0];
                mma16(gh, ah, bh0, bh1);
                mma16(ge, ah, bl0, bl1);
                mma16(ge, al, bh0, bh1);
            }
            int dc0 = nt * 8 + 2 * t4, dc1 = dc0 + 1;
            float b0 = sm[BG1_ + dc0], b1 = sm[BG1_ + dc1];
            float g0 = gelu_exact(gh[0] + ge[0] + b0);
            float g1 = gelu_exact(gh[1] + ge[1] + b1);
            float g2 = gelu_exact(gh[2] + ge[2] + b0);
            float g3 = gelu_exact(gh[3] + ge[3] + b1);
            int kpT = nt * 4 + t4;
            unsigned short h0, l0, h1, l1;
            bsplit(g0, h0, l0); bsplit(g1, h1, l1);
            su[G1h_ + ra0 * 36 + kpT] = pk16(h0, h1);
            su[G1l_ + ra0 * 36 + kpT] = pk16(l0, l1);
            bsplit(g2, h0, l0); bsplit(g3, h1, l1);
            su[G1h_ + ra1 * 36 + kpT] = pk16(h0, h1);
            su[G1l_ + ra1 * 36 + kpT] = pk16(l0, l1);
        }
        __syncthreads();

        // ---- F: out = Wg2 G1 + bg2 + res ; maxpool over group dim ----
        {
            int ra0 = mt * 16 + qg, ra1 = ra0 + 8;
            int n0 = nt * 8 + qg;
            float fh[4] = {0, 0, 0, 0}, fe[4] = {0, 0, 0, 0};
#pragma unroll
            for (int kt = 0; kt < 4; ++kt) {
                int kp0 = kt * 8 + t4, kp1 = kp0 + 4;
                unsigned ah[4], al[4];
                ah[0] = su[G1h_ + ra0 * 36 + kp0];
                ah[1] = su[G1h_ + ra1 * 36 + kp0];
                ah[2] = su[G1h_ + ra0 * 36 + kp1];
                ah[3] = su[G1h_ + ra1 * 36 + kp1];
                al[0] = su[G1l_ + ra0 * 36 + kp0];
                al[1] = su[G1l_ + ra1 * 36 + kp0];
                al[2] = su[G1l_ + ra0 * 36 + kp1];
                al[3] = su[G1l_ + ra1 * 36 + kp1];
                unsigned bh0 = su[WG2h_ + kp0 * 72 + n0];
                unsigned bh1 = su[WG2h_ + kp1 * 72 + n0];
                unsigned bl0 = su[WG2l_ + kp0 * 72 + n0];
                unsigned bl1 = su[WG2l_ + kp1 * 72 + n0];
                mma16(fh, ah, bh0, bh1);
                mma16(fe, ah, bl0, bl1);
                mma16(fe, al, bh0, bh1);
            }
            int dc0 = nt * 8 + 2 * t4, dc1 = dc0 + 1;
            float v0 = fh[0] + fe[0] + sm[BG2_ + dc0] + r0;
            float v1 = fh[1] + fe[1] + sm[BG2_ + dc1] + r1;
            float v2 = fh[2] + fe[2] + sm[BG2_ + dc0] + r2;
            float v3 = fh[3] + fe[3] + sm[BG2_ + dc1] + r3;
            float m0 = fmaxf(v0, v2), m1 = fmaxf(v1, v3);
#pragma unroll
            for (int off = 4; off < 32; off <<= 1) {
                m0 = fmaxf(m0, __shfl_xor_sync(FULLMASK, m0, off));
                m1 = fmaxf(m1, __shfl_xor_sync(FULLMASK, m1, off));
            }
            if (lane < 4) {
                sm[MP_ + mt * 64 + nt * 8 + 2 * t4]     = m0;
                sm[MP_ + mt * 64 + nt * 8 + 2 * t4 + 1] = m1;
            }
        }
        __syncthreads();
        if (tid < 64)
            out[(size_t)g * 67 + 3 + tid] =
                fmaxf(sm[MP_ + tid], sm[MP_ + 64 + tid]);
        __syncthreads();
    }
}

// ============================ launch ======================================
extern "C" void kernel_launch(void* const* d_in, const int* in_sizes, int n_in,
                              void* d_out, int out_size) {
    (void)in_sizes; (void)n_in; (void)out_size;
    const float* x        = (const float*)d_in[0];
    const float* w_alpha  = (const float*)d_in[1];
    const float* b_alpha  = (const float*)d_in[2];
    const float* bn_gamma = (const float*)d_in[3];
    const float* bn_beta  = (const float*)d_in[4];
    const float* bn_mean  = (const float*)d_in[5];
    const float* bn_var   = (const float*)d_in[6];
    const float* w_q      = (const float*)d_in[7];
    const float* b_q      = (const float*)d_in[8];
    const float* w_k      = (const float*)d_in[9];
    const float* b_k      = (const float*)d_in[10];
    const float* w_v      = (const float*)d_in[11];
    const float* b_v      = (const float*)d_in[12];
    const float* w_g1     = (const float*)d_in[13];
    const float* b_g1     = (const float*)d_in[14];
    const float* w_g2     = (const float*)d_in[15];
    const float* b_g2     = (const float*)d_in[16];
    float* out = (float*)d_out;

    cudaFuncSetAttribute(fps_kernel,
                         cudaFuncAttributeMaxDynamicSharedMemorySize, 49664);
    cudaFuncSetAttribute(knn_kernel,
                         cudaFuncAttributeMaxDynamicSharedMemorySize, 65536);
    cudaFuncSetAttribute(group_kernel,
                         cudaFuncAttributeMaxDynamicSharedMemorySize, SMTOT * 4);

    fps_kernel<<<B_, 512, 49664>>>(x, out);
    knn_kernel<<<B_ * 4, 512, 65536>>>(x);
    group_kernel<<<148, 512, SMTOT * 4>>>(w_alpha, b_alpha, bn_gamma, bn_beta,
                                          bn_mean, bn_var, w_q, b_q, w_k, b_k,
                                          w_v, b_v, w_g1, b_g1, w_g2, b_g2, out);
}

// round 7
// speedup vs baseline: 2.1471x; 1.1795x over previous
#include <cuda_runtime.h>
#include <math.h>

#define B_   32
#define N_   4096
#define S_   512
#define FULLMASK 0xffffffffu

__device__ float g_centroid[B_ * S_ * 3];
__device__ float g_groups[B_ * S_ * 96];   // [bs][c][k]

// ---------------- helpers -------------------------------------------------
__device__ __forceinline__ unsigned long long pk2(float lo, float hi) {
    unsigned long long r;
    asm("mov.b64 %0, {%1, %2};" : "=l"(r) : "f"(lo), "f"(hi));
    return r;
}
__device__ __forceinline__ void upk2(unsigned long long v, float& lo, float& hi) {
    asm("mov.b64 {%0, %1}, %2;" : "=f"(lo), "=f"(hi) : "l"(v));
}
__device__ __forceinline__ unsigned long long fma2_(unsigned long long a,
                                                   unsigned long long b,
                                                   unsigned long long c) {
    unsigned long long d;
    asm("fma.rn.f32x2 %0, %1, %2, %3;" : "=l"(d) : "l"(a), "l"(b), "l"(c));
    return d;
}
__device__ __forceinline__ unsigned short bh16(float x) {
    unsigned short r;
    asm("cvt.rn.bf16.f32 %0, %1;" : "=h"(r) : "f"(x));
    return r;
}
__device__ __forceinline__ float bf2f(unsigned short h) {
    return __uint_as_float((unsigned)h << 16);
}
__device__ __forceinline__ void bsplit(float x, unsigned short& h, unsigned short& l) {
    h = bh16(x);
    l = bh16(x - bf2f(h));
}
__device__ __forceinline__ unsigned pk16(unsigned short a, unsigned short b) {
    return (unsigned)a | ((unsigned)b << 16);
}
__device__ __forceinline__ unsigned bsplitw(float x) {
    unsigned short h, l;
    bsplit(x, h, l);
    return pk16(h, l);
}
__device__ __forceinline__ void mma16(float* c, const unsigned* a,
                                      unsigned b0, unsigned b1) {
    asm("mma.sync.aligned.m16n8k16.row.col.f32.bf16.bf16.f32 "
        "{%0,%1,%2,%3},{%4,%5,%6,%7},{%8,%9},{%0,%1,%2,%3};"
        : "+f"(c[0]), "+f"(c[1]), "+f"(c[2]), "+f"(c[3])
        : "r"(a[0]), "r"(a[1]), "r"(a[2]), "r"(a[3]), "r"(b0), "r"(b1));
}
__device__ __forceinline__ float gelu_exact(float v) {
    return 0.5f * v * (1.0f + erff(v * 0.70710678118654752440f));
}

// ============================ FPS =========================================
__global__ __launch_bounds__(512) void fps_kernel(const float* __restrict__ x,
                                                  float* __restrict__ out) {
    extern __shared__ float smf[];
    float* sx0 = smf;
    float* sx1 = smf + 4096;
    float* sx2 = smf + 8192;
    unsigned long long* pb = (unsigned long long*)(smf + 12288);

    int b = blockIdx.x, tid = threadIdx.x;
    int lane = tid & 31, warp = tid >> 5;
    const float* xb = x + (size_t)b * N_ * 3;

    float px[8], py[8], pz[8], dist[8];
#pragma unroll
    for (int i = 0; i < 8; ++i) {
        int n = tid + i * 512;
        float a0 = xb[n * 3 + 0], a1 = xb[n * 3 + 1], a2 = xb[n * 3 + 2];
        px[i] = a0; py[i] = a1; pz[i] = a2;
        sx0[n] = a0; sx1[n] = a1; sx2[n] = a2;
        dist[i] = 1e10f;
    }
    __syncthreads();

    int last = 0;
    for (int s = 0; s < S_; ++s) {
        float c0 = sx0[last], c1 = sx1[last], c2 = sx2[last];
        if (tid == 0) {
            int bs = b * S_ + s;
            out[(size_t)bs * 67 + 0] = c0;
            out[(size_t)bs * 67 + 1] = c1;
            out[(size_t)bs * 67 + 2] = c2;
            g_centroid[bs * 3 + 0] = c0;
            g_centroid[bs * 3 + 1] = c1;
            g_centroid[bs * 3 + 2] = c2;
        }
        float bv = -1.0f;
        unsigned bi = 0;
#pragma unroll
        for (int i = 0; i < 8; ++i) {
            float dx = px[i] - c0, dy = py[i] - c1, dz = pz[i] - c2;
            float d = (dx * dx + dy * dy) + dz * dz;
            float nd = fminf(dist[i], d);
            dist[i] = nd;
            if (nd > bv) { bv = nd; bi = (unsigned)(tid + i * 512); }
        }
        unsigned vb = __float_as_uint(bv);
        unsigned wmax = __reduce_max_sync(FULLMASK, vb);
        unsigned cand = (vb == wmax) ? bi : 0xffffffffu;
        unsigned widx = __reduce_min_sync(FULLMASK, cand);
        int par = s & 1;
        if (lane == 0)
            pb[par * 16 + warp] =
                ((unsigned long long)wmax << 32) |
                (unsigned long long)(0xffffffffu - widx);
        __syncthreads();
        // block reduce: 1 LDS.64 + 2 REDUX
        unsigned long long k = pb[par * 16 + (lane & 15)];
        unsigned kv = (unsigned)(k >> 32);
        unsigned bmax = __reduce_max_sync(FULLMASK, kv);
        unsigned enc = (kv == bmax) ? (unsigned)k : 0u;
        unsigned benc = __reduce_max_sync(FULLMASK, enc);
        last = (int)(0xffffffffu - benc);
    }
}

// ============================ KNN (2 centroids / warp) ====================
__global__ __launch_bounds__(512) void knn_kernel(const float* __restrict__ x) {
    int b    = blockIdx.x >> 2;
    int part = blockIdx.x & 3;
    extern __shared__ float smk[];
    float* sx0 = smk;
    float* sx1 = smk + 4096;
    float* sx2 = smk + 8192;
    float* sxs = smk + 12288;

    const float* xb = x + (size_t)b * N_ * 3;
    for (int i = threadIdx.x; i < N_; i += 512) {
        float a0 = xb[i * 3 + 0], a1 = xb[i * 3 + 1], a2 = xb[i * 3 + 2];
        sx0[i] = a0; sx1[i] = a1; sx2[i] = a2;
        sxs[i] = (a0 * a0 + a1 * a1) + a2 * a2;
    }
    __syncthreads();

    int warp = threadIdx.x >> 5, lane = threadIdx.x & 31;
    for (int jj = 0; jj < 4; ++jj) {
        int sA = part * 128 + jj * 32 + warp * 2;
        int bsA = b * S_ + sA, bsB = bsA + 1;
        float cA0 = g_centroid[bsA * 3 + 0], cA1 = g_centroid[bsA * 3 + 1],
              cA2 = g_centroid[bsA * 3 + 2];
        float cB0 = g_centroid[bsB * 3 + 0], cB1 = g_centroid[bsB * 3 + 1],
              cB2 = g_centroid[bsB * 3 + 2];
        float csA = (cA0 * cA0 + cA1 * cA1) + cA2 * cA2;
        float csB = (cB0 * cB0 + cB1 * cB1) + cB2 * cB2;

        float lvA = 3.402823466e38f, lvB = 3.402823466e38f;
        int   liA = -1, liB = -1;
        for (int base = 0; base < N_; base += 32) {
            int n = base + lane;
            float p0 = sx0[n], p1 = sx1[n], p2 = sx2[n], ps = sxs[n];
            float d2A = (csA + ps) - 2.0f * ((cA0 * p0 + cA1 * p1) + cA2 * p2);
            float d2B = (csB + ps) - 2.0f * ((cB0 * p0 + cB1 * p1) + cB2 * p2);

            float thr = __shfl_sync(FULLMASK, lvA, 31);
            unsigned m = __ballot_sync(FULLMASK, d2A < thr);
            while (m) {
                int src = __ffs(m) - 1;
                m &= m - 1;
                float cd = __shfl_sync(FULLMASK, d2A, src);
                int   cn = base + src;
                thr = __shfl_sync(FULLMASK, lvA, 31);
                if (cd < thr) {
                    unsigned keep = __ballot_sync(FULLMASK,
                        (lvA < cd) || (lvA == cd && liA < cn));
                    int pos = __popc(keep);
                    float pv = __shfl_up_sync(FULLMASK, lvA, 1);
                    int   pi = __shfl_up_sync(FULLMASK, liA, 1);
                    if (lane == pos)      { lvA = cd; liA = cn; }
                    else if (lane > pos)  { lvA = pv; liA = pi; }
                }
            }
            thr = __shfl_sync(FULLMASK, lvB, 31);
            m = __ballot_sync(FULLMASK, d2B < thr);
            while (m) {
                int src = __ffs(m) - 1;
                m &= m - 1;
                float cd = __shfl_sync(FULLMASK, d2B, src);
                int   cn = base + src;
                thr = __shfl_sync(FULLMASK, lvB, 31);
                if (cd < thr) {
                    unsigned keep = __ballot_sync(FULLMASK,
                        (lvB < cd) || (lvB == cd && liB < cn));
                    int pos = __popc(keep);
                    float pv = __shfl_up_sync(FULLMASK, lvB, 1);
                    int   pi = __shfl_up_sync(FULLMASK, liB, 1);
                    if (lane == pos)      { lvB = cd; liB = cn; }
                    else if (lane > pos)  { lvB = pv; liB = pi; }
                }
            }
        }
        float* gpA = g_groups + (size_t)bsA * 96;
        gpA[lane]      = sx0[liA] - cA0;
        gpA[32 + lane] = sx1[liA] - cA1;
        gpA[64 + lane] = sx2[liA] - cA2;
        float* gpB = g_groups + (size_t)bsB * 96;
        gpB[lane]      = sx0[liB] - cB0;
        gpB[32 + lane] = sx1[liB] - cB1;
        gpB[64 + lane] = sx2[liB] - cB2;
    }
}

// ================= per-group compute: 2 groups / iteration ================
// word offsets in dynamic smem
#define PBh_   0        // [kp_cc=32][c=64] stride 72
#define PBl_   2304
#define WVh_   4608     // [kp_c=32][d=64] stride 72
#define WVl_   6912
#define WG1h_  9216
#define WG1l_  11520
#define WG2h_  13824
#define WG2l_  16128
#define WA_    18432    // scaled w_alpha [c=3][d=64]
#define WQKB_  18624
#define BV_    18752
#define BG1_   18816
#define BG2_   18880
#define BA_    18944    // folded bias (ba*sc + sh)
#define BNM_   19008
#define BNR_   19072
#define BNG_   19136
#define BNB_   19200
#define CB_    19264
#define H32_   19272    // f32 [d=64][row=64] stride 68 -> 4352
#define Hh_    23624    // u32 [row=64][kp=32] stride 36 -> 2304
#define Hl_    25928
#define Uh_    28232    // u32 [kp_c=32][row=64] stride 72 -> 2304
#define Ul_    30536
#define Vh_    32840    // u32 [kp=32][d=64] stride 72 -> 2304
#define Vl_    35144
#define ATTh_  37448    // u32 [row=64][kp=16] stride 20 -> 1280
#define ATTl_  38728
#define Th_    40008    // u32 [row=64][kp=32] stride 36 -> 2304
#define Tl_    42312
#define G1h_   44616
#define G1l_   46920
#define LG_    49224    // f32 [row=64][j=32] stride 33 -> 2112
#define RBs_   51336    // 64
#define CAs_   51400    // 64
#define MP_    51464    // 2 x 128
#define SMTOT  51720    // words -> 206880 bytes
// init scratch (overlaps activation region)
#define SCRQ_  19272
#define SCRK_  23368
#define SCRP_  27464

__global__ __launch_bounds__(512) void group_kernel(
    const float* __restrict__ w_alpha, const float* __restrict__ b_alpha,
    const float* __restrict__ bn_gamma, const float* __restrict__ bn_beta,
    const float* __restrict__ bn_mean,  const float* __restrict__ bn_var,
    const float* __restrict__ w_q, const float* __restrict__ b_q,
    const float* __restrict__ w_k, const float* __restrict__ b_k,
    const float* __restrict__ w_v, const float* __restrict__ b_v,
    const float* __restrict__ w_g1, const float* __restrict__ b_g1,
    const float* __restrict__ w_g2, const float* __restrict__ b_g2,
    float* __restrict__ out) {
    extern __shared__ float sm[];
    unsigned* su = (unsigned*)sm;
    int tid = threadIdx.x;
    int warp = tid >> 5, lane = tid & 31;
    int qg = lane >> 2, t4 = lane & 3;

    // ---- init phase 1 ----
    for (int i = tid; i < 4096; i += 512) {
        sm[SCRQ_ + i] = w_q[i];
        sm[SCRK_ + i] = w_k[i];
    }
    for (int i = tid; i < 2048; i += 512) {
        int d = i >> 5, cp = i & 31;
        int i0 = d * 64 + 2 * cp;
        unsigned short h0, l0, h1, l1;
        bsplit(w_v[i0], h0, l0); bsplit(w_v[i0 + 1], h1, l1);
        su[WVh_ + cp * 72 + d] = pk16(h0, h1);
        su[WVl_ + cp * 72 + d] = pk16(l0, l1);
        bsplit(w_g1[i0], h0, l0); bsplit(w_g1[i0 + 1], h1, l1);
        su[WG1h_ + cp * 72 + d] = pk16(h0, h1);
        su[WG1l_ + cp * 72 + d] = pk16(l0, l1);
        bsplit(w_g2[i0], h0, l0); bsplit(w_g2[i0 + 1], h1, l1);
        su[WG2h_ + cp * 72 + d] = pk16(h0, h1);
        su[WG2l_ + cp * 72 + d] = pk16(l0, l1);
    }
    if (tid < 64) {
        sm[BV_ + tid] = b_v[tid];
        sm[BG1_ + tid] = b_g1[tid]; sm[BG2_ + tid] = b_g2[tid];
        sm[BA_ + tid] = b_alpha[tid];
        sm[BNM_ + tid] = bn_mean[tid];
        sm[BNR_ + tid] = rsqrtf(bn_var[tid] + 1e-5f);
        sm[BNG_ + tid] = bn_gamma[tid];
        sm[BNB_ + tid] = bn_beta[tid];
    }
    __syncthreads();

    // ---- init phase 2: P, folded biases, scaled W_alpha ----
    for (int i = tid; i < 4096; i += 512) {
        int c = i & 63, cc = i >> 6;
        float s = 0.f;
#pragma unroll 8
        for (int d = 0; d < 64; ++d)
            s += sm[SCRQ_ + d * 64 + c] * sm[SCRK_ + d * 64 + cc];
        sm[SCRP_ + cc * 64 + c] = s;
    }
    if (tid < 192) {
        int d = tid / 3, c = tid % 3;
        float sc = sm[BNR_ + d] * sm[BNG_ + d];
        sm[WA_ + c * 64 + d] = w_alpha[tid] * sc;
    }
    if (tid >= 192 && tid < 256) {
        int d = tid - 192;
        float sc = sm[BNR_ + d] * sm[BNG_ + d];
        float sh = sm[BNB_ + d] - sm[BNM_ + d] * sc;
        sm[BA_ + d] = sm[BA_ + d] * sc + sh;   // folded
    }
    if (tid >= 256 && tid < 320) {
        int c = tid - 256;
        float aq = 0.f, ak = 0.f;
#pragma unroll 8
        for (int d = 0; d < 64; ++d) {
            aq += sm[SCRQ_ + d * 64 + c] * b_k[d];
            ak += sm[SCRK_ + d * 64 + c] * b_q[d];
        }
        sm[WQKB_ + 2 * c]     = ak;
        sm[WQKB_ + 2 * c + 1] = aq;
    }
    if (tid == 511) {
        float s = 0.f;
        for (int d = 0; d < 64; ++d) s += b_q[d] * b_k[d];
        sm[CB_] = s;
    }
    __syncthreads();

    // ---- init phase 3: P -> split bf16 ----
    for (int i = tid; i < 2048; i += 512) {
        int ccp = i >> 6, c = i & 63;
        unsigned short h0, l0, h1, l1;
        bsplit(sm[SCRP_ + (2 * ccp) * 64 + c], h0, l0);
        bsplit(sm[SCRP_ + (2 * ccp + 1) * 64 + c], h1, l1);
        su[PBh_ + ccp * 72 + c] = pk16(h0, h1);
        su[PBl_ + ccp * 72 + c] = pk16(l0, l1);
    }
    __syncthreads();

    int mt0 = warp >> 3, nt = warp & 7;
    int agrp = warp & 1, ad8 = (warp >> 1) * 8;   // A-stage mapping

    for (int p = blockIdx.x; p < B_ * S_ / 2; p += gridDim.x) {
        // ---- A: h = gelu(BN(W_alpha g + b_alpha)), 8 d per warp ----
        {
            const float* gp = g_groups + ((size_t)(2 * p + agrp)) * 96;
            float gc0 = __ldg(gp + lane);
            float gc1 = __ldg(gp + 32 + lane);
            float gc2 = __ldg(gp + 64 + lane);
            int row = agrp * 32 + lane;
            float hv[8];
#pragma unroll
            for (int r = 0; r < 8; ++r) {
                int d = ad8 + r;
                float v = sm[WA_ + d] * gc0 + sm[WA_ + 64 + d] * gc1 +
                          sm[WA_ + 128 + d] * gc2 + sm[BA_ + d];
                v = gelu_exact(v);
                hv[r] = v;
                sm[H32_ + d * 68 + row] = v;
            }
#pragma unroll
            for (int r = 0; r < 4; ++r) {
                unsigned short h0, l0, h1, l1;
                bsplit(hv[2 * r], h0, l0); bsplit(hv[2 * r + 1], h1, l1);
                int kp = (ad8 >> 1) + r;
                su[Hh_ + row * 36 + kp] = pk16(h0, h1);
                su[Hl_ + row * 36 + kp] = pk16(l0, l1);
            }
        }
        __syncthreads();

        // ---- B: u = P h ; v = Wv h + bv  (M=64, per warp 2 row-tiles) ----
        {
            int n0 = nt * 8 + qg;
            int cc0 = nt * 8 + 2 * t4, cc1 = cc0 + 1;
            float bv0 = sm[BV_ + cc0], bv1 = sm[BV_ + cc1];
            int kpU = nt * 4 + t4;
#pragma unroll
            for (int t = 0; t < 2; ++t) {
                int rb = mt0 * 16 + t * 32;
                int ra0 = rb + qg, ra1 = ra0 + 8;
                float uh[4] = {0, 0, 0, 0}, ue[4] = {0, 0, 0, 0};
                float vh[4] = {0, 0, 0, 0}, ve[4] = {0, 0, 0, 0};
#pragma unroll
                for (int kt = 0; kt < 4; ++kt) {
                    int kp0 = kt * 8 + t4, kp1 = kp0 + 4;
                    unsigned ah[4], al[4];
                    ah[0] = su[Hh_ + ra0 * 36 + kp0];
                    ah[1] = su[Hh_ + ra1 * 36 + kp0];
                    ah[2] = su[Hh_ + ra0 * 36 + kp1];
                    ah[3] = su[Hh_ + ra1 * 36 + kp1];
                    al[0] = su[Hl_ + ra0 * 36 + kp0];
                    al[1] = su[Hl_ + ra1 * 36 + kp0];
                    al[2] = su[Hl_ + ra0 * 36 + kp1];
                    al[3] = su[Hl_ + ra1 * 36 + kp1];
                    unsigned bh0 = su[PBh_ + kp0 * 72 + n0];
                    unsigned bh1 = su[PBh_ + kp1 * 72 + n0];
                    unsigned bl0 = su[PBl_ + kp0 * 72 + n0];
                    unsigned bl1 = su[PBl_ + kp1 * 72 + n0];
                    mma16(uh, ah, bh0, bh1);
                    mma16(ue, ah, bl0, bl1);
                    mma16(ue, al, bh0, bh1);
                    bh0 = su[WVh_ + kp0 * 72 + n0];
                    bh1 = su[WVh_ + kp1 * 72 + n0];
                    bl0 = su[WVl_ + kp0 * 72 + n0];
                    bl1 = su[WVl_ + kp1 * 72 + n0];
                    mma16(vh, ah, bh0, bh1);
                    mma16(ve, ah, bl0, bl1);
                    mma16(ve, al, bh0, bh1);
                }
                float u0 = uh[0] + ue[0], u1 = uh[1] + ue[1];
                float u2 = uh[2] + ue[2], u3 = uh[3] + ue[3];
                float v0 = vh[0] + ve[0] + bv0, v1 = vh[1] + ve[1] + bv1;
                float v2 = vh[2] + ve[2] + bv0, v3 = vh[3] + ve[3] + bv1;
                unsigned short h0, l0, h1, l1;
                bsplit(u0, h0, l0); bsplit(u1, h1, l1);
                su[Uh_ + kpU * 72 + ra0] = pk16(h0, h1);
                su[Ul_ + kpU * 72 + ra0] = pk16(l0, l1);
                bsplit(u2, h0, l0); bsplit(u3, h1, l1);
                su[Uh_ + kpU * 72 + ra1] = pk16(h0, h1);
                su[Ul_ + kpU * 72 + ra1] = pk16(l0, l1);
                unsigned s0 = bsplitw(v0), s1 = bsplitw(v1);
                unsigned s2 = bsplitw(v2), s3 = bsplitw(v3);
                unsigned p0 = __shfl_xor_sync(FULLMASK, s0, 4);
                unsigned p1 = __shfl_xor_sync(FULLMASK, s1, 4);
                unsigned p2 = __shfl_xor_sync(FULLMASK, s2, 4);
                unsigned p3 = __shfl_xor_sync(FULLMASK, s3, 4);
                if ((qg & 1) == 0) {
                    int kv0 = t * 16 + mt0 * 8 + (qg >> 1);
                    int kv1 = kv0 + 4;
                    su[Vh_ + kv0 * 72 + cc0] = __byte_perm(s0, p0, 0x5410);
                    su[Vl_ + kv0 * 72 + cc0] = __byte_perm(s0, p0, 0x7632);
                    su[Vh_ + kv0 * 72 + cc1] = __byte_perm(s1, p1, 0x5410);
                    su[Vl_ + kv0 * 72 + cc1] = __byte_perm(s1, p1, 0x7632);
                    su[Vh_ + kv1 * 72 + cc0] = __byte_perm(s2, p2, 0x5410);
                    su[Vl_ + kv1 * 72 + cc0] = __byte_perm(s2, p2, 0x7632);
                    su[Vh_ + kv1 * 72 + cc1] = __byte_perm(s3, p3, 0x5410);
                    su[Vl_ + kv1 * 72 + cc1] = __byte_perm(s3, p3, 0x7632);
                }
            }
        }
        if (warp < 2) {   // bias dot products per group (fp32 exact)
            int grp = warp;
            unsigned long long rc = 0;
#pragma unroll 8
            for (int cc = 0; cc < 64; ++cc) {
                float hv = sm[H32_ + cc * 68 + grp * 32 + lane];
                rc = fma2_(*(const unsigned long long*)&sm[WQKB_ + 2 * cc],
                           pk2(hv, hv), rc);
            }
            float rB, cA;
            upk2(rc, rB, cA);
            sm[RBs_ + grp * 32 + lane] = rB;
            sm[CAs_ + grp * 32 + lane] = cA;
        }
        __syncthreads();

        // ---- C: logits = h^T u  (16 warps, 1 tile each) ----
        {
            int grp = warp >> 3, cmt = (warp >> 2) & 1, cnt = warp & 3;
            int ra0 = grp * 32 + cmt * 16 + qg, ra1 = ra0 + 8;
            int n0 = grp * 32 + cnt * 8 + qg;
            float ch[4] = {0, 0, 0, 0}, ce[4] = {0, 0, 0, 0};
#pragma unroll
            for (int kt = 0; kt < 4; ++kt) {
                int kp0 = kt * 8 + t4, kp1 = kp0 + 4;
                unsigned ah[4], al[4];
                ah[0] = su[Hh_ + ra0 * 36 + kp0];
                ah[1] = su[Hh_ + ra1 * 36 + kp0];
                ah[2] = su[Hh_ + ra0 * 36 + kp1];
                ah[3] = su[Hh_ + ra1 * 36 + kp1];
                al[0] = su[Hl_ + ra0 * 36 + kp0];
                al[1] = su[Hl_ + ra1 * 36 + kp0];
                al[2] = su[Hl_ + ra0 * 36 + kp1];
                al[3] = su[Hl_ + ra1 * 36 + kp1];
                unsigned bh0 = su[Uh_ + kp0 * 72 + n0];
                unsigned bh1 = su[Uh_ + kp1 * 72 + n0];
                unsigned bl0 = su[Ul_ + kp0 * 72 + n0];
                unsigned bl1 = su[Ul_ + kp1 * 72 + n0];
                mma16(ch, ah, bh0, bh1);
                mma16(ce, ah, bl0, bl1);
                mma16(ce, al, bh0, bh1);
            }
            int jc0 = cnt * 8 + 2 * t4;
            sm[LG_ + ra0 * 33 + jc0]     = ch[0] + ce[0];
            sm[LG_ + ra0 * 33 + jc0 + 1] = ch[1] + ce[1];
            sm[LG_ + ra1 * 33 + jc0]     = ch[2] + ce[2];
            sm[LG_ + ra1 * 33 + jc0 + 1] = ch[3] + ce[3];
        }
        __syncthreads();

        // ---- softmax: 4 rows per warp ----
        {
            float cb = sm[CB_];
#pragma unroll
            for (int k = 0; k < 4; ++k) {
                int r = warp + 16 * k;
                int grp = r >> 5, i = r & 31;
                float a = (sm[LG_ + r * 33 + lane] + sm[CAs_ + grp * 32 + i] +
                           sm[RBs_ + grp * 32 + lane] + cb) * 0.125f;
                float m = a;
#pragma unroll
                for (int off = 16; off; off >>= 1)
                    m = fmaxf(m, __shfl_xor_sync(FULLMASK, m, off));
                float e = expf(a - m);
                float s = e;
#pragma unroll
                for (int off = 16; off; off >>= 1)
                    s += __shfl_xor_sync(FULLMASK, s, off);
                float pf = e / s;
                unsigned w0 = bsplitw(pf);
                unsigned q0 = __shfl_xor_sync(FULLMASK, w0, 1);
                if ((lane & 1) == 0) {
                    int jp = lane >> 1;
                    su[ATTh_ + r * 20 + jp] = __byte_perm(w0, q0, 0x5410);
                    su[ATTl_ + r * 20 + jp] = __byte_perm(w0, q0, 0x7632);
                }
            }
        }
        __syncthreads();

        // ---- D: res = attn v ; T = res + h ----
        float rr[8];
        {
            int n0 = nt * 8 + qg;
            int dc0 = nt * 8 + 2 * t4, dc1 = dc0 + 1;
            int kpT = nt * 4 + t4;
#pragma unroll
            for (int grp = 0; grp < 2; ++grp) {
                int ra0 = grp * 32 + mt0 * 16 + qg, ra1 = ra0 + 8;
                float rh[4] = {0, 0, 0, 0}, re[4] = {0, 0, 0, 0};
#pragma unroll
                for (int kt = 0; kt < 2; ++kt) {
                    int kp0 = kt * 8 + t4, kp1 = kp0 + 4;
                    unsigned ah[4], al[4];
                    ah[0] = su[ATTh_ + ra0 * 20 + kp0];
                    ah[1] = su[ATTh_ + ra1 * 20 + kp0];
                    ah[2] = su[ATTh_ + ra0 * 20 + kp1];
                    ah[3] = su[ATTh_ + ra1 * 20 + kp1];
                    al[0] = su[ATTl_ + ra0 * 20 + kp0];
                    al[1] = su[ATTl_ + ra1 * 20 + kp0];
                    al[2] = su[ATTl_ + ra0 * 20 + kp1];
                    al[3] = su[ATTl_ + ra1 * 20 + kp1];
                    int kg0 = grp * 16 + kp0, kg1 = grp * 16 + kp1;
                    unsigned bh0 = su[Vh_ + kg0 * 72 + n0];
                    unsigned bh1 = su[Vh_ + kg1 * 72 + n0];
                    unsigned bl0 = su[Vl_ + kg0 * 72 + n0];
                    unsigned bl1 = su[Vl_ + kg1 * 72 + n0];
                    mma16(rh, ah, bh0, bh1);
                    mma16(re, ah, bl0, bl1);
                    mma16(re, al, bh0, bh1);
                }
                float r0 = rh[0] + re[0], r1 = rh[1] + re[1];
                float r2 = rh[2] + re[2], r3 = rh[3] + re[3];
                rr[grp * 4 + 0] = r0; rr[grp * 4 + 1] = r1;
                rr[grp * 4 + 2] = r2; rr[grp * 4 + 3] = r3;
                float t0 = r0 + sm[H32_ + dc0 * 68 + ra0];
                float t1 = r1 + sm[H32_ + dc1 * 68 + ra0];
                float t2 = r2 + sm[H32_ + dc0 * 68 + ra1];
                float t3 = r3 + sm[H32_ + dc1 * 68 + ra1];
                unsigned short h0, l0, h1, l1;
                bsplit(t0, h0, l0); bsplit(t1, h1, l1);
                su[Th_ + ra0 * 36 + kpT] = pk16(h0, h1);
                su[Tl_ + ra0 * 36 + kpT] = pk16(l0, l1);
                bsplit(t2, h0, l0); bsplit(t3, h1, l1);
                su[Th_ + ra1 * 36 + kpT] = pk16(h0, h1);
                su[Tl_ + ra1 * 36 + kpT] = pk16(l0, l1);
            }
        }
        __syncthreads();

        // ---- E: G1 = gelu(Wg1 T + bg1) (M=64) ----
        {
            int n0 = nt * 8 + qg;
            int dc0 = nt * 8 + 2 * t4, dc1 = dc0 + 1;
            float b0 = sm[BG1_ + dc0], b1 = sm[BG1_ + dc1];
            int kpT = nt * 4 + t4;
#pragma unroll
            for (int t = 0; t < 2; ++t) {
                int ra0 = t * 32 + mt0 * 16 + qg, ra1 = ra0 + 8;
                float gh[4] = {0, 0, 0, 0}, ge[4] = {0, 0, 0, 0};
#pragma unroll
                for (int kt = 0; kt < 4; ++kt) {
                    int kp0 = kt * 8 + t4, kp1 = kp0 + 4;
                    unsigned ah[4], al[4];
                    ah[0] = su[Th_ + ra0 * 36 + kp0];
                    ah[1] = su[Th_ + ra1 * 36 + kp0];
                    ah[2] = su[Th_ + ra0 * 36 + kp1];
                    ah[3] = su[Th_ + ra1 * 36 + kp1];
                    al[0] = su[Tl_ + ra0 * 36 + kp0];
                    al[1] = su[Tl_ + ra1 * 36 + kp0];
                    al[2] = su[Tl_ + ra0 * 36 + kp1];
                    al[3] = su[Tl_ + ra1 * 36 + kp1];
                    unsigned bh0 = su[WG1h_ + kp0 * 72 + n0];
                    unsigned bh1 = su[WG1h_ + kp1 * 72 + n0];
                    unsigned bl0 = su[WG1l_ + kp0 * 72 + n0];
                    unsigned bl1 = su[WG1l_ + kp1 * 72 + n0];
                    mma16(gh, ah, bh0, bh1);
                    mma16(ge, ah, bl0, bl1);
                    mma16(ge, al, bh0, bh1);
                }
                float g0 = gelu_exact(gh[0] + ge[0] + b0);
                float g1 = gelu_exact(gh[1] + ge[1] + b1);
                float g2 = gelu_exact(gh[2] + ge[2] + b0);
                float g3 = gelu_exact(gh[3] + ge[3] + b1);
                unsigned short h0, l0, h1, l1;
                bsplit(g0, h0, l0); bsplit(g1, h1, l1);
                su[G1h_ + ra0 * 36 + kpT] = pk16(h0, h1);
                su[G1l_ + ra0 * 36 + kpT] = pk16(l0, l1);
                bsplit(g2, h0, l0); bsplit(g3, h1, l1);
                su[G1h_ + ra1 * 36 + kpT] = pk16(h0, h1);
                su[G1l_ + ra1 * 36 + kpT] = pk16(l0, l1);
            }
        }
        __syncthreads();

        // ---- F: out = Wg2 G1 + bg2 + res ; maxpool ----
        {
            int n0 = nt * 8 + qg;
            int dc0 = nt * 8 + 2 * t4, dc1 = dc0 + 1;
            float b0 = sm[BG2_ + dc0], b1 = sm[BG2_ + dc1];
#pragma unroll
            for (int t = 0; t < 2; ++t) {
                int ra0 = t * 32 + mt0 * 16 + qg, ra1 = ra0 + 8;
                float fh[4] = {0, 0, 0, 0}, fe[4] = {0, 0, 0, 0};
#pragma unroll
                for (int kt = 0; kt < 4; ++kt) {
                    int kp0 = kt * 8 + t4, kp1 = kp0 + 4;
                    unsigned ah[4], al[4];
                    ah[0] = su[G1h_ + ra0 * 36 + kp0];
                    ah[1] = su[G1h_ + ra1 * 36 + kp0];
                    ah[2] = su[G1h_ + ra0 * 36 + kp1];
                    ah[3] = su[G1h_ + ra1 * 36 + kp1];
                    al[0] = su[G1l_ + ra0 * 36 + kp0];
                    al[1] = su[G1l_ + ra1 * 36 + kp0];
                    al[2] = su[G1l_ + ra0 * 36 + kp1];
                    al[3] = su[G1l_ + ra1 * 36 + kp1];
                    unsigned bh0 = su[WG2h_ + kp0 * 72 + n0];
                    unsigned bh1 = su[WG2h_ + kp1 * 72 + n0];
                    unsigned bl0 = su[WG2l_ + kp0 * 72 + n0];
                    unsigned bl1 = su[WG2l_ + kp1 * 72 + n0];
                    mma16(fh, ah, bh0, bh1);
                    mma16(fe, ah, bl0, bl1);
                    mma16(fe, al, bh0, bh1);
                }
                float v0 = fh[0] + fe[0] + b0 + rr[t * 4 + 0];
                float v1 = fh[1] + fe[1] + b1 + rr[t * 4 + 1];
                float v2 = fh[2] + fe[2] + b0 + rr[t * 4 + 2];
                float v3 = fh[3] + fe[3] + b1 + rr[t * 4 + 3];
                float m0 = fmaxf(v0, v2), m1 = fmaxf(v1, v3);
#pragma unroll
                for (int off = 4; off < 32; off <<= 1) {
                    m0 = fmaxf(m0, __shfl_xor_sync(FULLMASK, m0, off));
                    m1 = fmaxf(m1, __shfl_xor_sync(FULLMASK, m1, off));
                }
                if (lane < 4) {
                    sm[MP_ + t * 128 + mt0 * 64 + nt * 8 + 2 * t4]     = m0;
                    sm[MP_ + t * 128 + mt0 * 64 + nt * 8 + 2 * t4 + 1] = m1;
                }
            }
        }
        __syncthreads();
        if (tid < 128) {
            int grp = tid >> 6, d = tid & 63;
            out[(size_t)(2 * p + grp) * 67 + 3 + d] =
                fmaxf(sm[MP_ + grp * 128 + d], sm[MP_ + grp * 128 + 64 + d]);
        }
        __syncthreads();
    }
}

// ============================ launch ======================================
extern "C" void kernel_launch(void* const* d_in, const int* in_sizes, int n_in,
                              void* d_out, int out_size) {
    (void)in_sizes; (void)n_in; (void)out_size;
    const float* x        = (const float*)d_in[0];
    const float* w_alpha  = (const float*)d_in[1];
    const float* b_alpha  = (const float*)d_in[2];
    const float* bn_gamma = (const float*)d_in[3];
    const float* bn_beta  = (const float*)d_in[4];
    const float* bn_mean  = (const float*)d_in[5];
    const float* bn_var   = (const float*)d_in[6];
    const float* w_q      = (const float*)d_in[7];
    const float* b_q      = (const float*)d_in[8];
    const float* w_k      = (const float*)d_in[9];
    const float* b_k      = (const float*)d_in[10];
    const float* w_v      = (const float*)d_in[11];
    const float* b_v      = (const float*)d_in[12];
    const float* w_g1     = (const float*)d_in[13];
    const float* b_g1     = (const float*)d_in[14];
    const float* w_g2     = (const float*)d_in[15];
    const float* b_g2     = (const float*)d_in[16];
    float* out = (float*)d_out;

    cudaFuncSetAttribute(fps_kernel,
                         cudaFuncAttributeMaxDynamicSharedMemorySize, 49664);
    cudaFuncSetAttribute(knn_kernel,
                         cudaFuncAttributeMaxDynamicSharedMemorySize, 65536);
    cudaFuncSetAttribute(group_kernel,
                         cudaFuncAttributeMaxDynamicSharedMemorySize, SMTOT * 4);

    fps_kernel<<<B_, 512, 49664>>>(x, out);
    knn_kernel<<<B_ * 4, 512, 65536>>>(x);
    group_kernel<<<148, 512, SMTOT * 4>>>(w_alpha, b_alpha, bn_gamma, bn_beta,
                                          bn_mean, bn_var, w_q, b_q, w_k, b_k,
                                          w_v, b_v, w_g1, b_g1, w_g2, b_g2, out);
}